// round 11
// baseline (speedup 1.0000x reference)
#include <cuda_runtime.h>
#include <cuda_fp16.h>
#include <cstdint>

#define NB 2
#define NN 2048
#define NM 2048
#define ND 1024
#define NH 16
#define NK 64
#define NV 64

// ---------------- scratch (__device__ globals; no allocs allowed) ----------
__device__ __half g_Xh[(size_t)NB*NN*ND],   g_Xl[(size_t)NB*NN*ND];
__device__ __half g_Mh[(size_t)NB*NM*ND],   g_Ml[(size_t)NB*NM*ND];
__device__ __half g_Pqh[(size_t)NH*ND*NK],  g_Pql[(size_t)NH*ND*NK];
__device__ __half g_Pkh[(size_t)ND*NK],     g_Pkl[(size_t)ND*NK];
__device__ __half g_Pvh[(size_t)ND*NV],     g_Pvl[(size_t)ND*NV];
__device__ __half g_Poh[(size_t)NH*ND*NV],  g_Pol[(size_t)NH*ND*NV];
__device__ __half g_Qh[(size_t)NB*NH*NN*NK], g_Ql[(size_t)NB*NH*NN*NK];
__device__ __half g_Kh[(size_t)NB*NM*NK],   g_Kl[(size_t)NB*NM*NK];
__device__ __half g_Vh[(size_t)NB*NM*NV],   g_Vl[(size_t)NB*NM*NV];
__device__ __half g_Oh[(size_t)NB*NN*NH*NV], g_Ol[(size_t)NB*NN*NH*NV];

// ---------------- helpers --------------------------------------------------
__device__ __forceinline__ uint32_t smem_u32(const void* p) {
    uint32_t a;
    asm("{ .reg .u64 t; cvta.to.shared.u64 t, %1; cvt.u32.u64 %0, t; }" : "=r"(a) : "l"(p));
    return a;
}
__device__ __forceinline__ void ldsm_x4(uint32_t (&r)[4], uint32_t a) {
    asm volatile("ldmatrix.sync.aligned.m8n8.x4.shared.b16 {%0,%1,%2,%3}, [%4];"
                 : "=r"(r[0]), "=r"(r[1]), "=r"(r[2]), "=r"(r[3]) : "r"(a));
}
__device__ __forceinline__ void ldsm_x4t(uint32_t (&r)[4], uint32_t a) {
    asm volatile("ldmatrix.sync.aligned.m8n8.x4.trans.shared.b16 {%0,%1,%2,%3}, [%4];"
                 : "=r"(r[0]), "=r"(r[1]), "=r"(r[2]), "=r"(r[3]) : "r"(a));
}
__device__ __forceinline__ void mma16816(float (&c)[4], const uint32_t (&a)[4],
                                         uint32_t b0, uint32_t b1) {
    asm volatile("mma.sync.aligned.m16n8k16.row.col.f32.f16.f16.f32 "
                 "{%0,%1,%2,%3}, {%4,%5,%6,%7}, {%8,%9}, {%0,%1,%2,%3};"
                 : "+f"(c[0]), "+f"(c[1]), "+f"(c[2]), "+f"(c[3])
                 : "r"(a[0]), "r"(a[1]), "r"(a[2]), "r"(a[3]), "r"(b0), "r"(b1));
}
__device__ __forceinline__ uint32_t ex2_h2(uint32_t x) {
    uint32_t r;
    asm volatile("ex2.approx.f16x2 %0, %1;" : "=r"(r) : "r"(x));
    return r;
}
__device__ __forceinline__ void split2(float a, float b, __half* hp, __half* lp) {
    __half h0 = __float2half_rn(a), h1 = __float2half_rn(b);
    *(__half2*)hp = __halves2half2(h0, h1);
    *(__half2*)lp = __halves2half2(__float2half_rn(a - __half2float(h0)),
                                   __float2half_rn(b - __half2float(h1)));
}
#define CP_COMMIT() asm volatile("cp.async.commit_group;" ::: "memory")
#define CP_WAIT1()  asm volatile("cp.async.wait_group 1;" ::: "memory")
#define CP_WAIT0()  asm volatile("cp.async.wait_group 0;" ::: "memory")
#define PF_L2(p)    asm volatile("prefetch.global.L2 [%0];" :: "l"(p))

// swizzled 128B-row f16 tile loader (64 halves per row) — sync version
__device__ __forceinline__ void load_f16_tile(char* s, const __half* g,
                                              int gstride, int rows) {
    for (int i = threadIdx.x; i < rows * 8; i += 256) {
        int row = i >> 3, c = i & 7;
        uint4 v = *(const uint4*)(g + (size_t)row * gstride + c * 8);
        int off = row * 128 + c * 16;
        *(uint4*)(s + (off ^ ((off >> 3) & 0x70))) = v;
    }
}
// cp.async version
__device__ __forceinline__ void load_f16_tile_cp(uint32_t sbase, const __half* g,
                                                 int gstride, int rows) {
    for (int i = threadIdx.x; i < rows * 8; i += 256) {
        int row = i >> 3, c = i & 7;
        int off = row * 128 + c * 16;
        asm volatile("cp.async.cg.shared.global [%0], [%1], 16;"
                     :: "r"(sbase + (off ^ ((off >> 3) & 0x70))),
                        "l"(g + (size_t)row * gstride + c * 8) : "memory");
    }
}
// fragment address helpers (swizzle folded)
__device__ __forceinline__ uint32_t a_addr(uint32_t base, int row0, int ks, int lane) {
    int m = lane >> 3;
    int r = row0 + ((m & 1) << 3) + (lane & 7);
    int cb = ((((m >> 1) << 3) + (ks << 4)) << 1);
    return base + r * 128 + (cb ^ ((r & 7) << 4));
}
// x4 pair: lanes 0-15 -> fragment j, lanes 16-31 -> fragment j+1 (B in [n][k])
__device__ __forceinline__ uint32_t b_addr2(uint32_t base, int j, int ks, int lane) {
    int jj = j + (lane >> 4);
    int l = lane & 15;
    int r = (jj << 3) + (l & 7);
    int cb = (((ks << 4) + ((l >> 3) << 3)) << 1);
    return base + r * 128 + (cb ^ ((l & 7) << 4));
}
// x4 trans pair: lanes 0-15 -> jv, lanes 16-31 -> jv+1 (B in [k][n])
__device__ __forceinline__ uint32_t v_addr2(uint32_t base, int ks, int jv, int lane) {
    int jj = jv + (lane >> 4);
    int l = lane & 15;
    int r = (ks << 4) + l;
    int cb = (jj << 4);
    return base + r * 128 + (cb ^ ((l & 7) << 4));
}

// ---------------------------------------------------------------------------
// Kernel 0: fp32 -> fp16 hi/lo split, ALL tensors in one launch (grid.y = tensor)
// ---------------------------------------------------------------------------
__global__ void split_all_kernel(const float* __restrict__ X, const float* __restrict__ Mi,
                                 const float* __restrict__ Pq, const float* __restrict__ Pk,
                                 const float* __restrict__ Pv, const float* __restrict__ Po) {
    const float* s; __half* hp; __half* lp; size_t n;
    switch (blockIdx.y) {
        case 0: s = X;  hp = g_Xh;  lp = g_Xl;  n = (size_t)NB*NN*ND; break;
        case 1: s = Mi; hp = g_Mh;  lp = g_Ml;  n = (size_t)NB*NM*ND; break;
        case 2: s = Pq; hp = g_Pqh; lp = g_Pql; n = (size_t)NH*ND*NK; break;
        case 3: s = Pk; hp = g_Pkh; lp = g_Pkl; n = (size_t)ND*NK;    break;
        case 4: s = Pv; hp = g_Pvh; lp = g_Pvl; n = (size_t)ND*NV;    break;
        default:s = Po; hp = g_Poh; lp = g_Pol; n = (size_t)NH*ND*NV; break;
    }
    int n4 = (int)(n / 4);
    for (int i = blockIdx.x * blockDim.x + threadIdx.x; i < n4;
         i += gridDim.x * blockDim.x) {
        float4 v = ((const float4*)s)[i];
        split2(v.x, v.y, hp + 4*i,     lp + 4*i);
        split2(v.z, v.w, hp + 4*i + 2, lp + 4*i + 2);
    }
}

// ---------------------------------------------------------------------------
// Shared HMMA core, 2-stage cp.async pipeline, paired x4 B loads.
// ---------------------------------------------------------------------------
#define GST    49152
#define G_SA_H 0
#define G_SA_L 16384
#define G_SB_H 32768
#define G_SB_L 40960
#define SMEM_G 98304

template <bool TB>
__device__ __forceinline__ void gemm128x64(const __half* Ah, const __half* Al, int lda,
                                           const __half* Bh, const __half* Bl, int ldb,
                                           size_t bstep, int nchunks, float (&c)[8][4]) {
    extern __shared__ char smem[];
    uint32_t sb = smem_u32(smem);
    int lane = threadIdx.x & 31, w = threadIdx.x >> 5, wrow0 = w * 16;

    {
        uint32_t st = sb;
        load_f16_tile_cp(st + G_SA_H, Ah, lda, 128);
        load_f16_tile_cp(st + G_SA_L, Al, lda, 128);
        load_f16_tile_cp(st + G_SB_H, Bh, ldb, 64);
        load_f16_tile_cp(st + G_SB_L, Bl, ldb, 64);
        CP_COMMIT();
    }
    for (int ch = 0; ch < nchunks; ch++) {
        if (ch + 1 < nchunks) {
            uint32_t st = sb + ((ch + 1) & 1) * GST;
            load_f16_tile_cp(st + G_SA_H, Ah + (ch + 1) * 64, lda, 128);
            load_f16_tile_cp(st + G_SA_L, Al + (ch + 1) * 64, lda, 128);
            load_f16_tile_cp(st + G_SB_H, Bh + (ch + 1) * bstep, ldb, 64);
            load_f16_tile_cp(st + G_SB_L, Bl + (ch + 1) * bstep, ldb, 64);
            CP_COMMIT();
            CP_WAIT1();
        } else {
            CP_WAIT0();
        }
        __syncthreads();
        uint32_t st = sb + (ch & 1) * GST;
#pragma unroll
        for (int ks = 0; ks < 4; ks++) {
            uint32_t ah[4], al[4];
            ldsm_x4(ah, a_addr(st + G_SA_H, wrow0, ks, lane));
            ldsm_x4(al, a_addr(st + G_SA_L, wrow0, ks, lane));
#pragma unroll
            for (int j = 0; j < 8; j += 2) {
                uint32_t bh[4], bl[4];
                if (TB) {
                    ldsm_x4t(bh, v_addr2(st + G_SB_H, ks, j, lane));
                    ldsm_x4t(bl, v_addr2(st + G_SB_L, ks, j, lane));
                } else {
                    ldsm_x4(bh, b_addr2(st + G_SB_H, j, ks, lane));
                    ldsm_x4(bl, b_addr2(st + G_SB_L, j, ks, lane));
                }
                mma16816(c[j],   ah, bh[0], bh[1]);
                mma16816(c[j],   al, bh[0], bh[1]);
                mma16816(c[j],   ah, bl[0], bl[1]);
                mma16816(c[j+1], ah, bh[2], bh[3]);
                mma16816(c[j+1], al, bh[2], bh[3]);
                mma16816(c[j+1], ah, bl[2], bl[3]);
            }
        }
        __syncthreads();
    }
}

// ---------------------------------------------------------------------------
// Kernel 1: Q projection. grid (NN/128, NH, NB)
// ---------------------------------------------------------------------------
__global__ void __launch_bounds__(256, 2)
q_proj_kernel() {
    int b = blockIdx.z, h = blockIdx.y, n0 = blockIdx.x * 128;
    float c[8][4] = {};
    gemm128x64<true>(g_Xh + (size_t)(b*NN + n0)*ND, g_Xl + (size_t)(b*NN + n0)*ND, ND,
                     g_Pqh + (size_t)h*ND*NK, g_Pql + (size_t)h*ND*NK, NK,
                     (size_t)64*NK, ND/64, c);
    int lane = threadIdx.x & 31, w = threadIdx.x >> 5;
    int gid = lane >> 2, t4 = lane & 3;
    int grow0 = n0 + w*16 + gid;
    size_t r0 = ((size_t)(b*NH + h)*NN + grow0)*NK;
#pragma unroll
    for (int j = 0; j < 8; j++) {
        int col = 8*j + 2*t4;
        split2(c[j][0], c[j][1], &g_Qh[r0 + col], &g_Ql[r0 + col]);
        split2(c[j][2], c[j][3], &g_Qh[r0 + 8*NK + col], &g_Ql[r0 + 8*NK + col]);
    }
}

// ---------------------------------------------------------------------------
// Kernel 2: K/V projection. grid (NM/128, 2(sel), NB)
// ---------------------------------------------------------------------------
__global__ void __launch_bounds__(256, 2)
kv_proj_kernel() {
    int b = blockIdx.z, sel = blockIdx.y, m0 = blockIdx.x * 128;
    const __half* Bh = sel ? g_Pvh : g_Pkh;
    const __half* Bl = sel ? g_Pvl : g_Pkl;
    float c[8][4] = {};
    gemm128x64<true>(g_Mh + (size_t)(b*NM + m0)*ND, g_Ml + (size_t)(b*NM + m0)*ND, ND,
                     Bh, Bl, NK, (size_t)64*NK, ND/64, c);
    __half* Ch = sel ? g_Vh : g_Kh;
    __half* Cl = sel ? g_Vl : g_Kl;
    int lane = threadIdx.x & 31, w = threadIdx.x >> 5;
    int gid = lane >> 2, t4 = lane & 3;
    int grow0 = m0 + w*16 + gid;
    size_t r0 = (size_t)(b*NM + grow0)*NK;
#pragma unroll
    for (int j = 0; j < 8; j++) {
        int col = 8*j + 2*t4;
        split2(c[j][0], c[j][1], &Ch[r0 + col], &Cl[r0 + col]);
        split2(c[j][2], c[j][3], &Ch[r0 + 8*NK + col], &Cl[r0 + 8*NK + col]);
    }
}

// ---------------------------------------------------------------------------
// Kernel 3: mma.sync flash attention.
//   3-stage cp.async K/V pipeline, ONE barrier per iteration (issue placed
//   after the barrier so stage (it+2)%3 writes can't race laggard readers),
//   mask loaded as the S-accumulator INIT (overlaps LDG latency with MMA),
//   paired x4 B loads, L2 mask prefetch 2 iters ahead, V-hi-only PV.
// Stage (24KB): KH 0, KL 8K, VH 16K; stages at 0/24K/48K. Q at 72K/88K. 104KB.
// ---------------------------------------------------------------------------
#define AST    24576
#define A_KH   0
#define A_KL   8192
#define A_VH   16384
#define S_QH   73728
#define S_QL   90112
#define SMEM_ATT 106496
#define L2E 1.4426950408889634f

__global__ void __launch_bounds__(256, 2)
attn_kernel(const float* __restrict__ mask) {
    extern __shared__ char smem[];
    const uint32_t sb = smem_u32(smem);
    const int tid = threadIdx.x;
    const int w = tid >> 5, lane = tid & 31;
    const int gid = lane >> 2, t4 = lane & 3;
    const int wrow0 = w * 16;
    const int b = blockIdx.z, h = blockIdx.y, n0 = blockIdx.x * 128;

    const __half* kh_g = g_Kh + (size_t)b*NM*NK;
    const __half* kl_g = g_Kl + (size_t)b*NM*NK;
    const __half* vh_g = g_Vh + (size_t)b*NM*NV;

    // per-lane mask prefetch pointer: 32 lanes cover this warp's 16 rows x 64 cols
    const float* pfb = mask + ((size_t)(b*NH + h)*NN + n0 + wrow0 + (lane >> 1))*(size_t)NM
                            + (lane & 1) * 32;

    // prologue: stages 0 and 1
    load_f16_tile_cp(sb + A_KH, kh_g, NK, 64);
    load_f16_tile_cp(sb + A_KL, kl_g, NK, 64);
    load_f16_tile_cp(sb + A_VH, vh_g, NV, 64);
    CP_COMMIT();
    load_f16_tile_cp(sb + AST + A_KH, kh_g + (size_t)64*NK, NK, 64);
    load_f16_tile_cp(sb + AST + A_KL, kl_g + (size_t)64*NK, NK, 64);
    load_f16_tile_cp(sb + AST + A_VH, vh_g + (size_t)64*NV, NV, 64);
    CP_COMMIT();
    PF_L2(pfb);
    PF_L2(pfb + 64);

    size_t qoff = ((size_t)(b*NH + h)*NN + n0) * NK;
    load_f16_tile((char*)smem + S_QH, g_Qh + qoff, NK, 128);
    load_f16_tile((char*)smem + S_QL, g_Ql + qoff, NK, 128);
    __syncthreads();

    uint32_t qh[4][4];
#pragma unroll
    for (int ks = 0; ks < 4; ks++) ldsm_x4(qh[ks], a_addr(sb + S_QH, wrow0, ks, lane));

    float o[8][4];
#pragma unroll
    for (int j = 0; j < 8; j++) { o[j][0]=0.f; o[j][1]=0.f; o[j][2]=0.f; o[j][3]=0.f; }
    float gmax0 = -1e30f, gmax1 = -1e30f, gs0 = 0.f, gs1 = 0.f;

    const int grow0 = n0 + wrow0 + gid;
    const float* mp0 = mask + (((size_t)(b*NH + h)*NN + grow0))*(size_t)NM + 2*t4;
    const float* mp1 = mp0 + (size_t)8 * NM;

    const int NIT = NM / 64;
    for (int it = 0; it < NIT; it++) {
        const int m0 = it * 64;
        // wait for this iter's stage (own copies), then CTA-wide visibility
        if (it + 1 < NIT) CP_WAIT1(); else CP_WAIT0();
        __syncthreads();
        // issue stage it+2 AFTER the barrier (safe vs laggard readers of it-1)
        if (it + 2 < NIT) {
            int st3 = (it + 2) % 3;
            uint32_t st = sb + st3 * AST;
            const int m2 = m0 + 128;
            load_f16_tile_cp(st + A_KH, kh_g + (size_t)m2*NK, NK, 64);
            load_f16_tile_cp(st + A_KL, kl_g + (size_t)m2*NK, NK, 64);
            load_f16_tile_cp(st + A_VH, vh_g + (size_t)m2*NV, NV, 64);
            CP_COMMIT();
            PF_L2(pfb + m2);
        }
        const uint32_t st = sb + (it % 3) * AST;

        // ---- S accumulator initialized with the mask (overlaps LDG w/ MMA)
        float c[8][4];
#pragma unroll
        for (int j = 0; j < 8; j++) {
            float2 a = *(const float2*)(mp0 + m0 + 8*j);
            float2 d = *(const float2*)(mp1 + m0 + 8*j);
            c[j][0] = a.x; c[j][1] = a.y; c[j][2] = d.x; c[j][3] = d.y;
        }
#pragma unroll
        for (int ks = 0; ks < 4; ks++) {
            uint32_t ql[4];
            ldsm_x4(ql, a_addr(sb + S_QL, wrow0, ks, lane));
#pragma unroll
            for (int j = 0; j < 8; j += 2) {
                uint32_t bh[4], bl[4];
                ldsm_x4(bh, b_addr2(st + A_KH, j, ks, lane));
                ldsm_x4(bl, b_addr2(st + A_KL, j, ks, lane));
                mma16816(c[j],   qh[ks], bh[0], bh[1]);
                mma16816(c[j],   ql,     bh[0], bh[1]);
                mma16816(c[j],   qh[ks], bl[0], bl[1]);
                mma16816(c[j+1], qh[ks], bh[2], bh[3]);
                mma16816(c[j+1], ql,     bh[2], bh[3]);
                mma16816(c[j+1], qh[ks], bl[2], bl[3]);
            }
        }

        float mx0 = -1e30f, mx1 = -1e30f;
#pragma unroll
        for (int j = 0; j < 8; j++) {
            mx0 = fmaxf(mx0, fmaxf(c[j][0], c[j][1]));
            mx1 = fmaxf(mx1, fmaxf(c[j][2], c[j][3]));
        }
        mx0 = fmaxf(mx0, __shfl_xor_sync(0xffffffffu, mx0, 1));
        mx0 = fmaxf(mx0, __shfl_xor_sync(0xffffffffu, mx0, 2));
        mx1 = fmaxf(mx1, __shfl_xor_sync(0xffffffffu, mx1, 1));
        mx1 = fmaxf(mx1, __shfl_xor_sync(0xffffffffu, mx1, 2));

        float mn0 = fmaxf(gmax0, mx0), mn1 = fmaxf(gmax1, mx1);
        float sc0 = __expf(gmax0 - mn0), sc1 = __expf(gmax1 - mn1);
        gmax0 = mn0; gmax1 = mn1;

        uint32_t pk[8][2];
        float rs0 = 0.f, rs1 = 0.f;
#pragma unroll
        for (int j = 0; j < 8; j++) {
            __half2 t0 = __floats2half2_rn((c[j][0]-mn0)*L2E, (c[j][1]-mn0)*L2E);
            __half2 t1 = __floats2half2_rn((c[j][2]-mn1)*L2E, (c[j][3]-mn1)*L2E);
            pk[j][0] = ex2_h2(*(uint32_t*)&t0);
            pk[j][1] = ex2_h2(*(uint32_t*)&t1);
            float2 f0 = __half22float2(*(__half2*)&pk[j][0]);
            float2 f1 = __half22float2(*(__half2*)&pk[j][1]);
            rs0 += f0.x + f0.y; rs1 += f1.x + f1.y;
        }
        rs0 += __shfl_xor_sync(0xffffffffu, rs0, 1);
        rs0 += __shfl_xor_sync(0xffffffffu, rs0, 2);
        rs1 += __shfl_xor_sync(0xffffffffu, rs1, 1);
        rs1 += __shfl_xor_sync(0xffffffffu, rs1, 2);
        gs0 = gs0 * sc0 + rs0;
        gs1 = gs1 * sc1 + rs1;

#pragma unroll
        for (int j = 0; j < 8; j++) {
            o[j][0] *= sc0; o[j][1] *= sc0; o[j][2] *= sc1; o[j][3] *= sc1;
        }
#pragma unroll
        for (int ks = 0; ks < 4; ks++) {
            uint32_t pa[4] = { pk[2*ks][0], pk[2*ks][1], pk[2*ks+1][0], pk[2*ks+1][1] };
#pragma unroll
            for (int jv = 0; jv < 8; jv += 2) {
                uint32_t vh[4];
                ldsm_x4t(vh, v_addr2(st + A_VH, ks, jv, lane));
                mma16816(o[jv],   pa, vh[0], vh[1]);
                mma16816(o[jv+1], pa, vh[2], vh[3]);
            }
        }
    }

    // epilogue: normalize, split-store O as fp16 hi/lo [b][n][h][v]
    float inv0 = 1.0f / gs0, inv1 = 1.0f / gs1;
    size_t o0 = ((size_t)(b*NN + grow0)*NH + h)*NV + 2*t4;
    size_t o1 = ((size_t)(b*NN + grow0 + 8)*NH + h)*NV + 2*t4;
#pragma unroll
    for (int jv = 0; jv < 8; jv++) {
        split2(o[jv][0]*inv0, o[jv][1]*inv0, &g_Oh[o0 + 8*jv], &g_Ol[o0 + 8*jv]);
        split2(o[jv][2]*inv1, o[jv][3]*inv1, &g_Oh[o1 + 8*jv], &g_Ol[o1 + 8*jv]);
    }
}

// ---------------------------------------------------------------------------
// Kernel 4: output projection. grid (ND/64, NN/128, NB). Contraction = 16 heads.
// ---------------------------------------------------------------------------
__global__ void __launch_bounds__(256, 2)
out_proj_kernel(float* __restrict__ Y) {
    int b = blockIdx.z, n0 = blockIdx.y * 128, d0 = blockIdx.x * 64;
    float c[8][4] = {};
    gemm128x64<false>(g_Oh + (size_t)(b*NN + n0)*(NH*NV), g_Ol + (size_t)(b*NN + n0)*(NH*NV),
                      NH*NV,
                      g_Poh + (size_t)d0*NV, g_Pol + (size_t)d0*NV, NV,
                      (size_t)ND*NV, NH, c);
    int lane = threadIdx.x & 31, w = threadIdx.x >> 5;
    int gid = lane >> 2, t4 = lane & 3;
    int grow0 = n0 + w*16 + gid;
    size_t r0 = (size_t)(b*NN + grow0)*ND + d0;
#pragma unroll
    for (int j = 0; j < 8; j++) {
        int col = 8*j + 2*t4;
        *(float2*)&Y[r0 + col]        = make_float2(c[j][0], c[j][1]);
        *(float2*)&Y[r0 + 8*ND + col] = make_float2(c[j][2], c[j][3]);
    }
}

// ---------------------------------------------------------------------------
extern "C" void kernel_launch(void* const* d_in, const int* in_sizes, int n_in,
                              void* d_out, int out_size) {
    const float* X    = (const float*)d_in[0];
    const float* Mi   = (const float*)d_in[1];
    const float* mask = (const float*)d_in[2];
    const float* Pq   = (const float*)d_in[3];
    const float* Pk   = (const float*)d_in[4];
    const float* Pv   = (const float*)d_in[5];
    const float* Po   = (const float*)d_in[6];
    float* Y = (float*)d_out;

    cudaFuncSetAttribute(q_proj_kernel,   cudaFuncAttributeMaxDynamicSharedMemorySize, SMEM_G);
    cudaFuncSetAttribute(kv_proj_kernel,  cudaFuncAttributeMaxDynamicSharedMemorySize, SMEM_G);
    cudaFuncSetAttribute(attn_kernel,     cudaFuncAttributeMaxDynamicSharedMemorySize, SMEM_ATT);
    cudaFuncSetAttribute(out_proj_kernel, cudaFuncAttributeMaxDynamicSharedMemorySize, SMEM_G);

    split_all_kernel<<<dim3(2048, 6), 256>>>(X, Mi, Pq, Pk, Pv, Po);

    kv_proj_kernel<<<dim3(NM/128, 2, NB), 256, SMEM_G>>>();
    q_proj_kernel<<<dim3(NN/128, NH, NB), 256, SMEM_G>>>();
    attn_kernel<<<dim3(NN/128, NH, NB), 256, SMEM_ATT>>>(mask);
    out_proj_kernel<<<dim3(ND/64, NN/128, NB), 256, SMEM_G>>>(Y);
}

// round 12
// speedup vs baseline: 1.0086x; 1.0086x over previous
#include <cuda_runtime.h>
#include <cuda_fp16.h>
#include <cstdint>

#define NB 2
#define NN 2048
#define NM 2048
#define ND 1024
#define NH 16
#define NK 64
#define NV 64

// ---------------- scratch (__device__ globals; no allocs allowed) ----------
__device__ __half g_Xh[(size_t)NB*NN*ND],   g_Xl[(size_t)NB*NN*ND];
__device__ __half g_Mh[(size_t)NB*NM*ND],   g_Ml[(size_t)NB*NM*ND];
__device__ __half g_Pqh[(size_t)NH*ND*NK],  g_Pql[(size_t)NH*ND*NK];
__device__ __half g_Pkh[(size_t)ND*NK],     g_Pkl[(size_t)ND*NK];
__device__ __half g_Pvh[(size_t)ND*NV],     g_Pvl[(size_t)ND*NV];
__device__ __half g_Poh[(size_t)NH*ND*NV],  g_Pol[(size_t)NH*ND*NV];
__device__ __half g_Qh[(size_t)NB*NH*NN*NK], g_Ql[(size_t)NB*NH*NN*NK];
__device__ __half g_Kh[(size_t)NB*NM*NK],   g_Kl[(size_t)NB*NM*NK];
__device__ __half g_Vh[(size_t)NB*NM*NV],   g_Vl[(size_t)NB*NM*NV];
__device__ __half g_Oh[(size_t)NB*NN*NH*NV], g_Ol[(size_t)NB*NN*NH*NV];

// ---------------- helpers --------------------------------------------------
__device__ __forceinline__ uint32_t smem_u32(const void* p) {
    uint32_t a;
    asm("{ .reg .u64 t; cvta.to.shared.u64 t, %1; cvt.u32.u64 %0, t; }" : "=r"(a) : "l"(p));
    return a;
}
__device__ __forceinline__ void ldsm_x4(uint32_t (&r)[4], uint32_t a) {
    asm volatile("ldmatrix.sync.aligned.m8n8.x4.shared.b16 {%0,%1,%2,%3}, [%4];"
                 : "=r"(r[0]), "=r"(r[1]), "=r"(r[2]), "=r"(r[3]) : "r"(a));
}
__device__ __forceinline__ void ldsm_x4t(uint32_t (&r)[4], uint32_t a) {
    asm volatile("ldmatrix.sync.aligned.m8n8.x4.trans.shared.b16 {%0,%1,%2,%3}, [%4];"
                 : "=r"(r[0]), "=r"(r[1]), "=r"(r[2]), "=r"(r[3]) : "r"(a));
}
__device__ __forceinline__ void mma16816(float (&c)[4], const uint32_t (&a)[4],
                                         uint32_t b0, uint32_t b1) {
    asm volatile("mma.sync.aligned.m16n8k16.row.col.f32.f16.f16.f32 "
                 "{%0,%1,%2,%3}, {%4,%5,%6,%7}, {%8,%9}, {%0,%1,%2,%3};"
                 : "+f"(c[0]), "+f"(c[1]), "+f"(c[2]), "+f"(c[3])
                 : "r"(a[0]), "r"(a[1]), "r"(a[2]), "r"(a[3]), "r"(b0), "r"(b1));
}
__device__ __forceinline__ uint32_t ex2_h2(uint32_t x) {
    uint32_t r;
    asm volatile("ex2.approx.f16x2 %0, %1;" : "=r"(r) : "r"(x));
    return r;
}
__device__ __forceinline__ void split2(float a, float b, __half* hp, __half* lp) {
    __half h0 = __float2half_rn(a), h1 = __float2half_rn(b);
    *(__half2*)hp = __halves2half2(h0, h1);
    *(__half2*)lp = __halves2half2(__float2half_rn(a - __half2float(h0)),
                                   __float2half_rn(b - __half2float(h1)));
}
#define CP_COMMIT() asm volatile("cp.async.commit_group;" ::: "memory")
#define CP_WAIT1()  asm volatile("cp.async.wait_group 1;" ::: "memory")
#define CP_WAIT0()  asm volatile("cp.async.wait_group 0;" ::: "memory")
#define PF_L2(p)    asm volatile("prefetch.global.L2 [%0];" :: "l"(p))

// swizzled 128B-row f16 tile loader (64 halves per row) — sync version
__device__ __forceinline__ void load_f16_tile(char* s, const __half* g,
                                              int gstride, int rows) {
    for (int i = threadIdx.x; i < rows * 8; i += 256) {
        int row = i >> 3, c = i & 7;
        uint4 v = *(const uint4*)(g + (size_t)row * gstride + c * 8);
        int off = row * 128 + c * 16;
        *(uint4*)(s + (off ^ ((off >> 3) & 0x70))) = v;
    }
}
// cp.async version
__device__ __forceinline__ void load_f16_tile_cp(uint32_t sbase, const __half* g,
                                                 int gstride, int rows) {
    for (int i = threadIdx.x; i < rows * 8; i += 256) {
        int row = i >> 3, c = i & 7;
        int off = row * 128 + c * 16;
        asm volatile("cp.async.cg.shared.global [%0], [%1], 16;"
                     :: "r"(sbase + (off ^ ((off >> 3) & 0x70))),
                        "l"(g + (size_t)row * gstride + c * 8) : "memory");
    }
}
// fragment address helpers (swizzle folded)
__device__ __forceinline__ uint32_t a_addr(uint32_t base, int row0, int ks, int lane) {
    int m = lane >> 3;
    int r = row0 + ((m & 1) << 3) + (lane & 7);
    int cb = ((((m >> 1) << 3) + (ks << 4)) << 1);
    return base + r * 128 + (cb ^ ((r & 7) << 4));
}
// x4 pair: lanes 0-15 -> fragment j, lanes 16-31 -> fragment j+1 (B in [n][k])
__device__ __forceinline__ uint32_t b_addr2(uint32_t base, int j, int ks, int lane) {
    int jj = j + (lane >> 4);
    int l = lane & 15;
    int r = (jj << 3) + (l & 7);
    int cb = (((ks << 4) + ((l >> 3) << 3)) << 1);
    return base + r * 128 + (cb ^ ((l & 7) << 4));
}
// x4 trans pair: lanes 0-15 -> jv, lanes 16-31 -> jv+1 (B in [k][n])
__device__ __forceinline__ uint32_t v_addr2(uint32_t base, int ks, int jv, int lane) {
    int jj = jv + (lane >> 4);
    int l = lane & 15;
    int r = (ks << 4) + l;
    int cb = (jj << 4);
    return base + r * 128 + (cb ^ ((l & 7) << 4));
}

// ---------------------------------------------------------------------------
// Kernel 0: fp32 -> fp16 hi/lo split, ALL tensors in one launch (grid.y = tensor)
// ---------------------------------------------------------------------------
__global__ void split_all_kernel(const float* __restrict__ X, const float* __restrict__ Mi,
                                 const float* __restrict__ Pq, const float* __restrict__ Pk,
                                 const float* __restrict__ Pv, const float* __restrict__ Po) {
    const float* s; __half* hp; __half* lp; size_t n;
    switch (blockIdx.y) {
        case 0: s = X;  hp = g_Xh;  lp = g_Xl;  n = (size_t)NB*NN*ND; break;
        case 1: s = Mi; hp = g_Mh;  lp = g_Ml;  n = (size_t)NB*NM*ND; break;
        case 2: s = Pq; hp = g_Pqh; lp = g_Pql; n = (size_t)NH*ND*NK; break;
        case 3: s = Pk; hp = g_Pkh; lp = g_Pkl; n = (size_t)ND*NK;    break;
        case 4: s = Pv; hp = g_Pvh; lp = g_Pvl; n = (size_t)ND*NV;    break;
        default:s = Po; hp = g_Poh; lp = g_Pol; n = (size_t)NH*ND*NV; break;
    }
    int n4 = (int)(n / 4);
    for (int i = blockIdx.x * blockDim.x + threadIdx.x; i < n4;
         i += gridDim.x * blockDim.x) {
        float4 v = ((const float4*)s)[i];
        split2(v.x, v.y, hp + 4*i,     lp + 4*i);
        split2(v.z, v.w, hp + 4*i + 2, lp + 4*i + 2);
    }
}

// ---------------------------------------------------------------------------
// Shared HMMA core, 2-stage cp.async pipeline, paired x4 B loads.
// ---------------------------------------------------------------------------
#define GST    49152
#define G_SA_H 0
#define G_SA_L 16384
#define G_SB_H 32768
#define G_SB_L 40960
#define SMEM_G 98304

template <bool TB>
__device__ __forceinline__ void gemm128x64(const __half* Ah, const __half* Al, int lda,
                                           const __half* Bh, const __half* Bl, int ldb,
                                           size_t bstep, int nchunks, float (&c)[8][4]) {
    extern __shared__ char smem[];
    uint32_t sb = smem_u32(smem);
    int lane = threadIdx.x & 31, w = threadIdx.x >> 5, wrow0 = w * 16;

    {
        uint32_t st = sb;
        load_f16_tile_cp(st + G_SA_H, Ah, lda, 128);
        load_f16_tile_cp(st + G_SA_L, Al, lda, 128);
        load_f16_tile_cp(st + G_SB_H, Bh, ldb, 64);
        load_f16_tile_cp(st + G_SB_L, Bl, ldb, 64);
        CP_COMMIT();
    }
    for (int ch = 0; ch < nchunks; ch++) {
        if (ch + 1 < nchunks) {
            uint32_t st = sb + ((ch + 1) & 1) * GST;
            load_f16_tile_cp(st + G_SA_H, Ah + (ch + 1) * 64, lda, 128);
            load_f16_tile_cp(st + G_SA_L, Al + (ch + 1) * 64, lda, 128);
            load_f16_tile_cp(st + G_SB_H, Bh + (ch + 1) * bstep, ldb, 64);
            load_f16_tile_cp(st + G_SB_L, Bl + (ch + 1) * bstep, ldb, 64);
            CP_COMMIT();
            CP_WAIT1();
        } else {
            CP_WAIT0();
        }
        __syncthreads();
        uint32_t st = sb + (ch & 1) * GST;
#pragma unroll
        for (int ks = 0; ks < 4; ks++) {
            uint32_t ah[4], al[4];
            ldsm_x4(ah, a_addr(st + G_SA_H, wrow0, ks, lane));
            ldsm_x4(al, a_addr(st + G_SA_L, wrow0, ks, lane));
#pragma unroll
            for (int j = 0; j < 8; j += 2) {
                uint32_t bh[4], bl[4];
                if (TB) {
                    ldsm_x4t(bh, v_addr2(st + G_SB_H, ks, j, lane));
                    ldsm_x4t(bl, v_addr2(st + G_SB_L, ks, j, lane));
                } else {
                    ldsm_x4(bh, b_addr2(st + G_SB_H, j, ks, lane));
                    ldsm_x4(bl, b_addr2(st + G_SB_L, j, ks, lane));
                }
                mma16816(c[j],   ah, bh[0], bh[1]);
                mma16816(c[j],   al, bh[0], bh[1]);
                mma16816(c[j],   ah, bl[0], bl[1]);
                mma16816(c[j+1], ah, bh[2], bh[3]);
                mma16816(c[j+1], al, bh[2], bh[3]);
                mma16816(c[j+1], ah, bl[2], bl[3]);
            }
        }
        __syncthreads();
    }
}

// ---------------------------------------------------------------------------
// Kernel 1: Q projection. grid (NN/128, NH, NB)
// ---------------------------------------------------------------------------
__global__ void __launch_bounds__(256, 2)
q_proj_kernel() {
    int b = blockIdx.z, h = blockIdx.y, n0 = blockIdx.x * 128;
    float c[8][4] = {};
    gemm128x64<true>(g_Xh + (size_t)(b*NN + n0)*ND, g_Xl + (size_t)(b*NN + n0)*ND, ND,
                     g_Pqh + (size_t)h*ND*NK, g_Pql + (size_t)h*ND*NK, NK,
                     (size_t)64*NK, ND/64, c);
    int lane = threadIdx.x & 31, w = threadIdx.x >> 5;
    int gid = lane >> 2, t4 = lane & 3;
    int grow0 = n0 + w*16 + gid;
    size_t r0 = ((size_t)(b*NH + h)*NN + grow0)*NK;
#pragma unroll
    for (int j = 0; j < 8; j++) {
        int col = 8*j + 2*t4;
        split2(c[j][0], c[j][1], &g_Qh[r0 + col], &g_Ql[r0 + col]);
        split2(c[j][2], c[j][3], &g_Qh[r0 + 8*NK + col], &g_Ql[r0 + 8*NK + col]);
    }
}

// ---------------------------------------------------------------------------
// Kernel 2: K/V projection. grid (NM/128, 2(sel), NB)
// ---------------------------------------------------------------------------
__global__ void __launch_bounds__(256, 2)
kv_proj_kernel() {
    int b = blockIdx.z, sel = blockIdx.y, m0 = blockIdx.x * 128;
    const __half* Bh = sel ? g_Pvh : g_Pkh;
    const __half* Bl = sel ? g_Pvl : g_Pkl;
    float c[8][4] = {};
    gemm128x64<true>(g_Mh + (size_t)(b*NM + m0)*ND, g_Ml + (size_t)(b*NM + m0)*ND, ND,
                     Bh, Bl, NK, (size_t)64*NK, ND/64, c);
    __half* Ch = sel ? g_Vh : g_Kh;
    __half* Cl = sel ? g_Vl : g_Kl;
    int lane = threadIdx.x & 31, w = threadIdx.x >> 5;
    int gid = lane >> 2, t4 = lane & 3;
    int grow0 = m0 + w*16 + gid;
    size_t r0 = (size_t)(b*NM + grow0)*NK;
#pragma unroll
    for (int j = 0; j < 8; j++) {
        int col = 8*j + 2*t4;
        split2(c[j][0], c[j][1], &Ch[r0 + col], &Cl[r0 + col]);
        split2(c[j][2], c[j][3], &Ch[r0 + 8*NK + col], &Cl[r0 + 8*NK + col]);
    }
}

// ---------------------------------------------------------------------------
// Kernel 3: mma.sync flash attention — ROUND-10 pipeline (2-stage, cp.async
// issued inside previous compute window, two barriers/iter) + mask loaded
// as the S-accumulator INIT (overlaps mask LDG latency with the MMA stream).
// Stage (24KB): KH 0, KL 8K, VH 16K; stages at 0, 24K. Q at 48K/64K. 80KB.
// ---------------------------------------------------------------------------
#define AST    24576
#define A_KH   0
#define A_KL   8192
#define A_VH   16384
#define S_QH   49152
#define S_QL   65536
#define SMEM_ATT 81920
#define L2E 1.4426950408889634f

__global__ void __launch_bounds__(256, 2)
attn_kernel(const float* __restrict__ mask) {
    extern __shared__ char smem[];
    const uint32_t sb = smem_u32(smem);
    const int tid = threadIdx.x;
    const int w = tid >> 5, lane = tid & 31;
    const int gid = lane >> 2, t4 = lane & 3;
    const int wrow0 = w * 16;
    const int b = blockIdx.z, h = blockIdx.y, n0 = blockIdx.x * 128;

    const __half* kh_g = g_Kh + (size_t)b*NM*NK;
    const __half* kl_g = g_Kl + (size_t)b*NM*NK;
    const __half* vh_g = g_Vh + (size_t)b*NM*NV;

    // per-lane mask prefetch pointer: 32 lanes cover this warp's 16 rows x 64 cols
    const float* pfb = mask + ((size_t)(b*NH + h)*NN + n0 + wrow0 + (lane >> 1))*(size_t)NM
                            + (lane & 1) * 32;

    {
        load_f16_tile_cp(sb + A_KH, kh_g, NK, 64);
        load_f16_tile_cp(sb + A_KL, kl_g, NK, 64);
        load_f16_tile_cp(sb + A_VH, vh_g, NV, 64);
        CP_COMMIT();
        PF_L2(pfb);                       // iter-0 mask into L2
    }
    size_t qoff = ((size_t)(b*NH + h)*NN + n0) * NK;
    load_f16_tile((char*)smem + S_QH, g_Qh + qoff, NK, 128);
    load_f16_tile((char*)smem + S_QL, g_Ql + qoff, NK, 128);
    __syncthreads();

    uint32_t qh[4][4];
#pragma unroll
    for (int ks = 0; ks < 4; ks++) ldsm_x4(qh[ks], a_addr(sb + S_QH, wrow0, ks, lane));

    float o[8][4];
#pragma unroll
    for (int j = 0; j < 8; j++) { o[j][0]=0.f; o[j][1]=0.f; o[j][2]=0.f; o[j][3]=0.f; }
    float gmax0 = -1e30f, gmax1 = -1e30f, gs0 = 0.f, gs1 = 0.f;

    const int grow0 = n0 + wrow0 + gid;
    const float* mp0 = mask + (((size_t)(b*NH + h)*NN + grow0))*(size_t)NM + 2*t4;
    const float* mp1 = mp0 + (size_t)8 * NM;

    const int NIT = NM / 64;
    for (int it = 0; it < NIT; it++) {
        const int m0 = it * 64;
        if (it + 1 < NIT) {
            uint32_t st = sb + ((it + 1) & 1) * AST;
            const int m1 = m0 + 64;
            load_f16_tile_cp(st + A_KH, kh_g + (size_t)m1*NK, NK, 64);
            load_f16_tile_cp(st + A_KL, kl_g + (size_t)m1*NK, NK, 64);
            load_f16_tile_cp(st + A_VH, vh_g + (size_t)m1*NV, NV, 64);
            CP_COMMIT();
            PF_L2(pfb + m1);              // next iter's mask into L2
            CP_WAIT1();
        } else {
            CP_WAIT0();
        }
        __syncthreads();
        const uint32_t st = sb + (it & 1) * AST;

        // ---- S accumulator initialized with the mask (overlaps LDG w/ MMA)
        float c[8][4];
#pragma unroll
        for (int j = 0; j < 8; j++) {
            float2 a = *(const float2*)(mp0 + m0 + 8*j);
            float2 d = *(const float2*)(mp1 + m0 + 8*j);
            c[j][0] = a.x; c[j][1] = a.y; c[j][2] = d.x; c[j][3] = d.y;
        }
#pragma unroll
        for (int ks = 0; ks < 4; ks++) {
            uint32_t ql[4];
            ldsm_x4(ql, a_addr(sb + S_QL, wrow0, ks, lane));
#pragma unroll
            for (int j = 0; j < 8; j += 2) {
                uint32_t bh[4], bl[4];
                ldsm_x4(bh, b_addr2(st + A_KH, j, ks, lane));
                ldsm_x4(bl, b_addr2(st + A_KL, j, ks, lane));
                mma16816(c[j],   qh[ks], bh[0], bh[1]);
                mma16816(c[j],   ql,     bh[0], bh[1]);
                mma16816(c[j],   qh[ks], bl[0], bl[1]);
                mma16816(c[j+1], qh[ks], bh[2], bh[3]);
                mma16816(c[j+1], ql,     bh[2], bh[3]);
                mma16816(c[j+1], qh[ks], bl[2], bl[3]);
            }
        }

        float mx0 = -1e30f, mx1 = -1e30f;
#pragma unroll
        for (int j = 0; j < 8; j++) {
            mx0 = fmaxf(mx0, fmaxf(c[j][0], c[j][1]));
            mx1 = fmaxf(mx1, fmaxf(c[j][2], c[j][3]));
        }
        mx0 = fmaxf(mx0, __shfl_xor_sync(0xffffffffu, mx0, 1));
        mx0 = fmaxf(mx0, __shfl_xor_sync(0xffffffffu, mx0, 2));
        mx1 = fmaxf(mx1, __shfl_xor_sync(0xffffffffu, mx1, 1));
        mx1 = fmaxf(mx1, __shfl_xor_sync(0xffffffffu, mx1, 2));

        float mn0 = fmaxf(gmax0, mx0), mn1 = fmaxf(gmax1, mx1);
        float sc0 = __expf(gmax0 - mn0), sc1 = __expf(gmax1 - mn1);
        gmax0 = mn0; gmax1 = mn1;

        uint32_t pk[8][2];
        float rs0 = 0.f, rs1 = 0.f;
#pragma unroll
        for (int j = 0; j < 8; j++) {
            __half2 t0 = __floats2half2_rn((c[j][0]-mn0)*L2E, (c[j][1]-mn0)*L2E);
            __half2 t1 = __floats2half2_rn((c[j][2]-mn1)*L2E, (c[j][3]-mn1)*L2E);
            pk[j][0] = ex2_h2(*(uint32_t*)&t0);
            pk[j][1] = ex2_h2(*(uint32_t*)&t1);
            float2 f0 = __half22float2(*(__half2*)&pk[j][0]);
            float2 f1 = __half22float2(*(__half2*)&pk[j][1]);
            rs0 += f0.x + f0.y; rs1 += f1.x + f1.y;
        }
        rs0 += __shfl_xor_sync(0xffffffffu, rs0, 1);
        rs0 += __shfl_xor_sync(0xffffffffu, rs0, 2);
        rs1 += __shfl_xor_sync(0xffffffffu, rs1, 1);
        rs1 += __shfl_xor_sync(0xffffffffu, rs1, 2);
        gs0 = gs0 * sc0 + rs0;
        gs1 = gs1 * sc1 + rs1;

#pragma unroll
        for (int j = 0; j < 8; j++) {
            o[j][0] *= sc0; o[j][1] *= sc0; o[j][2] *= sc1; o[j][3] *= sc1;
        }
#pragma unroll
        for (int ks = 0; ks < 4; ks++) {
            uint32_t pa[4] = { pk[2*ks][0], pk[2*ks][1], pk[2*ks+1][0], pk[2*ks+1][1] };
#pragma unroll
            for (int jv = 0; jv < 8; jv += 2) {
                uint32_t vh[4];
                ldsm_x4t(vh, v_addr2(st + A_VH, ks, jv, lane));
                mma16816(o[jv],   pa, vh[0], vh[1]);
                mma16816(o[jv+1], pa, vh[2], vh[3]);
            }
        }
        __syncthreads();
    }

    // epilogue: normalize, split-store O as fp16 hi/lo [b][n][h][v]
    float inv0 = 1.0f / gs0, inv1 = 1.0f / gs1;
    size_t o0 = ((size_t)(b*NN + grow0)*NH + h)*NV + 2*t4;
    size_t o1 = ((size_t)(b*NN + grow0 + 8)*NH + h)*NV + 2*t4;
#pragma unroll
    for (int jv = 0; jv < 8; jv++) {
        split2(o[jv][0]*inv0, o[jv][1]*inv0, &g_Oh[o0 + 8*jv], &g_Ol[o0 + 8*jv]);
        split2(o[jv][2]*inv1, o[jv][3]*inv1, &g_Oh[o1 + 8*jv], &g_Ol[o1 + 8*jv]);
    }
}

// ---------------------------------------------------------------------------
// Kernel 4: output projection. grid (ND/64, NN/128, NB). Contraction = 16 heads.
// ---------------------------------------------------------------------------
__global__ void __launch_bounds__(256, 2)
out_proj_kernel(float* __restrict__ Y) {
    int b = blockIdx.z, n0 = blockIdx.y * 128, d0 = blockIdx.x * 64;
    float c[8][4] = {};
    gemm128x64<false>(g_Oh + (size_t)(b*NN + n0)*(NH*NV), g_Ol + (size_t)(b*NN + n0)*(NH*NV),
                      NH*NV,
                      g_Poh + (size_t)d0*NV, g_Pol + (size_t)d0*NV, NV,
                      (size_t)ND*NV, NH, c);
    int lane = threadIdx.x & 31, w = threadIdx.x >> 5;
    int gid = lane >> 2, t4 = lane & 3;
    int grow0 = n0 + w*16 + gid;
    size_t r0 = (size_t)(b*NN + grow0)*ND + d0;
#pragma unroll
    for (int j = 0; j < 8; j++) {
        int col = 8*j + 2*t4;
        *(float2*)&Y[r0 + col]        = make_float2(c[j][0], c[j][1]);
        *(float2*)&Y[r0 + 8*ND + col] = make_float2(c[j][2], c[j][3]);
    }
}

// ---------------------------------------------------------------------------
extern "C" void kernel_launch(void* const* d_in, const int* in_sizes, int n_in,
                              void* d_out, int out_size) {
    const float* X    = (const float*)d_in[0];
    const float* Mi   = (const float*)d_in[1];
    const float* mask = (const float*)d_in[2];
    const float* Pq   = (const float*)d_in[3];
    const float* Pk   = (const float*)d_in[4];
    const float* Pv   = (const float*)d_in[5];
    const float* Po   = (const float*)d_in[6];
    float* Y = (float*)d_out;

    cudaFuncSetAttribute(q_proj_kernel,   cudaFuncAttributeMaxDynamicSharedMemorySize, SMEM_G);
    cudaFuncSetAttribute(kv_proj_kernel,  cudaFuncAttributeMaxDynamicSharedMemorySize, SMEM_G);
    cudaFuncSetAttribute(attn_kernel,     cudaFuncAttributeMaxDynamicSharedMemorySize, SMEM_ATT);
    cudaFuncSetAttribute(out_proj_kernel, cudaFuncAttributeMaxDynamicSharedMemorySize, SMEM_G);

    split_all_kernel<<<dim3(2048, 6), 256>>>(X, Mi, Pq, Pk, Pv, Po);

    kv_proj_kernel<<<dim3(NM/128, 2, NB), 256, SMEM_G>>>();
    q_proj_kernel<<<dim3(NN/128, NH, NB), 256, SMEM_G>>>();
    attn_kernel<<<dim3(NN/128, NH, NB), 256, SMEM_ATT>>>(mask);
    out_proj_kernel<<<dim3(ND/64, NN/128, NB), 256, SMEM_G>>>(Y);
}

// round 13
// speedup vs baseline: 1.1058x; 1.0964x over previous
#include <cuda_runtime.h>
#include <cuda_fp16.h>
#include <cstdint>

#define NB 2
#define NN 2048
#define NM 2048
#define ND 1024
#define NH 16
#define NK 64
#define NV 64

// ---------------- scratch (__device__ globals; no allocs allowed) ----------
__device__ __half g_Xh[(size_t)NB*NN*ND],   g_Xl[(size_t)NB*NN*ND];
__device__ __half g_Mh[(size_t)NB*NM*ND],   g_Ml[(size_t)NB*NM*ND];
__device__ __half g_Pqh[(size_t)NH*ND*NK],  g_Pql[(size_t)NH*ND*NK];
__device__ __half g_Pkh[(size_t)ND*NK],     g_Pkl[(size_t)ND*NK];
__device__ __half g_Pvh[(size_t)ND*NV],     g_Pvl[(size_t)ND*NV];
__device__ __half g_Poh[(size_t)NH*ND*NV],  g_Pol[(size_t)NH*ND*NV];
__device__ __half g_Qh[(size_t)NB*NH*NN*NK], g_Ql[(size_t)NB*NH*NN*NK];
__device__ __half g_Kh[(size_t)NB*NM*NK],   g_Kl[(size_t)NB*NM*NK];
__device__ __half g_Vh[(size_t)NB*NM*NV];
__device__ __half g_Oh[(size_t)NB*NN*NH*NV], g_Ol[(size_t)NB*NN*NH*NV];

// ---------------- helpers --------------------------------------------------
__device__ __forceinline__ uint32_t smem_u32(const void* p) {
    uint32_t a;
    asm("{ .reg .u64 t; cvta.to.shared.u64 t, %1; cvt.u32.u64 %0, t; }" : "=r"(a) : "l"(p));
    return a;
}
__device__ __forceinline__ void ldsm_x4(uint32_t (&r)[4], uint32_t a) {
    asm volatile("ldmatrix.sync.aligned.m8n8.x4.shared.b16 {%0,%1,%2,%3}, [%4];"
                 : "=r"(r[0]), "=r"(r[1]), "=r"(r[2]), "=r"(r[3]) : "r"(a));
}
__device__ __forceinline__ void ldsm_x4t(uint32_t (&r)[4], uint32_t a) {
    asm volatile("ldmatrix.sync.aligned.m8n8.x4.trans.shared.b16 {%0,%1,%2,%3}, [%4];"
                 : "=r"(r[0]), "=r"(r[1]), "=r"(r[2]), "=r"(r[3]) : "r"(a));
}
__device__ __forceinline__ void mma16816(float (&c)[4], const uint32_t (&a)[4],
                                         uint32_t b0, uint32_t b1) {
    asm volatile("mma.sync.aligned.m16n8k16.row.col.f32.f16.f16.f32 "
                 "{%0,%1,%2,%3}, {%4,%5,%6,%7}, {%8,%9}, {%0,%1,%2,%3};"
                 : "+f"(c[0]), "+f"(c[1]), "+f"(c[2]), "+f"(c[3])
                 : "r"(a[0]), "r"(a[1]), "r"(a[2]), "r"(a[3]), "r"(b0), "r"(b1));
}
__device__ __forceinline__ uint32_t ex2_h2(uint32_t x) {
    uint32_t r;
    asm volatile("ex2.approx.f16x2 %0, %1;" : "=r"(r) : "r"(x));
    return r;
}
__device__ __forceinline__ void split2(float a, float b, __half* hp, __half* lp) {
    __half h0 = __float2half_rn(a), h1 = __float2half_rn(b);
    *(__half2*)hp = __halves2half2(h0, h1);
    *(__half2*)lp = __halves2half2(__float2half_rn(a - __half2float(h0)),
                                   __float2half_rn(b - __half2float(h1)));
}
#define CP_COMMIT() asm volatile("cp.async.commit_group;" ::: "memory")
#define CP_WAIT1()  asm volatile("cp.async.wait_group 1;" ::: "memory")
#define CP_WAIT0()  asm volatile("cp.async.wait_group 0;" ::: "memory")
#define PF_L2(p)    asm volatile("prefetch.global.L2 [%0];" :: "l"(p))

// swizzled 128B-row f16 tile loader (64 halves per row) — sync version
__device__ __forceinline__ void load_f16_tile(char* s, const __half* g,
                                              int gstride, int rows) {
    for (int i = threadIdx.x; i < rows * 8; i += 256) {
        int row = i >> 3, c = i & 7;
        uint4 v = *(const uint4*)(g + (size_t)row * gstride + c * 8);
        int off = row * 128 + c * 16;
        *(uint4*)(s + (off ^ ((off >> 3) & 0x70))) = v;
    }
}
// cp.async version
__device__ __forceinline__ void load_f16_tile_cp(uint32_t sbase, const __half* g,
                                                 int gstride, int rows) {
    for (int i = threadIdx.x; i < rows * 8; i += 256) {
        int row = i >> 3, c = i & 7;
        int off = row * 128 + c * 16;
        asm volatile("cp.async.cg.shared.global [%0], [%1], 16;"
                     :: "r"(sbase + (off ^ ((off >> 3) & 0x70))),
                        "l"(g + (size_t)row * gstride + c * 8) : "memory");
    }
}
// fragment address helpers (swizzle folded)
__device__ __forceinline__ uint32_t a_addr(uint32_t base, int row0, int ks, int lane) {
    int m = lane >> 3;
    int r = row0 + ((m & 1) << 3) + (lane & 7);
    int cb = ((((m >> 1) << 3) + (ks << 4)) << 1);
    return base + r * 128 + (cb ^ ((r & 7) << 4));
}
// x4 pair: lanes 0-15 -> fragment j, lanes 16-31 -> fragment j+1 (B in [n][k])
__device__ __forceinline__ uint32_t b_addr2(uint32_t base, int j, int ks, int lane) {
    int jj = j + (lane >> 4);
    int l = lane & 15;
    int r = (jj << 3) + (l & 7);
    int cb = (((ks << 4) + ((l >> 3) << 3)) << 1);
    return base + r * 128 + (cb ^ ((l & 7) << 4));
}
// x4 trans pair: lanes 0-15 -> jv, lanes 16-31 -> jv+1 (B in [k][n])
__device__ __forceinline__ uint32_t v_addr2(uint32_t base, int ks, int jv, int lane) {
    int jj = jv + (lane >> 4);
    int l = lane & 15;
    int r = (ks << 4) + l;
    int cb = (jj << 4);
    return base + r * 128 + (cb ^ ((l & 7) << 4));
}

// ---------------------------------------------------------------------------
// Kernel 0: fp32 -> fp16 hi/lo split, ALL tensors in one launch (grid.y = tensor)
// ---------------------------------------------------------------------------
__global__ void split_all_kernel(const float* __restrict__ X, const float* __restrict__ Mi,
                                 const float* __restrict__ Pq, const float* __restrict__ Pk,
                                 const float* __restrict__ Pv, const float* __restrict__ Po) {
    const float* s; __half* hp; __half* lp; size_t n;
    switch (blockIdx.y) {
        case 0: s = X;  hp = g_Xh;  lp = g_Xl;  n = (size_t)NB*NN*ND; break;
        case 1: s = Mi; hp = g_Mh;  lp = g_Ml;  n = (size_t)NB*NM*ND; break;
        case 2: s = Pq; hp = g_Pqh; lp = g_Pql; n = (size_t)NH*ND*NK; break;
        case 3: s = Pk; hp = g_Pkh; lp = g_Pkl; n = (size_t)ND*NK;    break;
        case 4: s = Pv; hp = g_Pvh; lp = g_Pvl; n = (size_t)ND*NV;    break;
        default:s = Po; hp = g_Poh; lp = g_Pol; n = (size_t)NH*ND*NV; break;
    }
    int n4 = (int)(n / 4);
    for (int i = blockIdx.x * blockDim.x + threadIdx.x; i < n4;
         i += gridDim.x * blockDim.x) {
        float4 v = ((const float4*)s)[i];
        split2(v.x, v.y, hp + 4*i,     lp + 4*i);
        split2(v.z, v.w, hp + 4*i + 2, lp + 4*i + 2);
    }
}

// ---------------------------------------------------------------------------
// Shared HMMA core, 2-stage cp.async pipeline, paired x4 B loads.
// P3=true: 3-pass split (ah*bh + al*bh + ah*bl). P3=false: 2-pass, B-lo
// never loaded (skips its cp.async traffic too).
// ---------------------------------------------------------------------------
#define GST    49152
#define G_SA_H 0
#define G_SA_L 16384
#define G_SB_H 32768
#define G_SB_L 40960
#define SMEM_G 98304

template <bool TB, bool P3>
__device__ __forceinline__ void gemm128x64(const __half* Ah, const __half* Al, int lda,
                                           const __half* Bh, const __half* Bl, int ldb,
                                           size_t bstep, int nchunks, float (&c)[8][4]) {
    extern __shared__ char smem[];
    uint32_t sb = smem_u32(smem);
    int lane = threadIdx.x & 31, w = threadIdx.x >> 5, wrow0 = w * 16;

    {
        uint32_t st = sb;
        load_f16_tile_cp(st + G_SA_H, Ah, lda, 128);
        load_f16_tile_cp(st + G_SA_L, Al, lda, 128);
        load_f16_tile_cp(st + G_SB_H, Bh, ldb, 64);
        if (P3) load_f16_tile_cp(st + G_SB_L, Bl, ldb, 64);
        CP_COMMIT();
    }
    for (int ch = 0; ch < nchunks; ch++) {
        if (ch + 1 < nchunks) {
            uint32_t st = sb + ((ch + 1) & 1) * GST;
            load_f16_tile_cp(st + G_SA_H, Ah + (ch + 1) * 64, lda, 128);
            load_f16_tile_cp(st + G_SA_L, Al + (ch + 1) * 64, lda, 128);
            load_f16_tile_cp(st + G_SB_H, Bh + (ch + 1) * bstep, ldb, 64);
            if (P3) load_f16_tile_cp(st + G_SB_L, Bl + (ch + 1) * bstep, ldb, 64);
            CP_COMMIT();
            CP_WAIT1();
        } else {
            CP_WAIT0();
        }
        __syncthreads();
        uint32_t st = sb + (ch & 1) * GST;
#pragma unroll
        for (int ks = 0; ks < 4; ks++) {
            uint32_t ah[4], al[4];
            ldsm_x4(ah, a_addr(st + G_SA_H, wrow0, ks, lane));
            ldsm_x4(al, a_addr(st + G_SA_L, wrow0, ks, lane));
#pragma unroll
            for (int j = 0; j < 8; j += 2) {
                uint32_t bh[4];
                if (TB) ldsm_x4t(bh, v_addr2(st + G_SB_H, ks, j, lane));
                else    ldsm_x4 (bh, b_addr2(st + G_SB_H, j, ks, lane));
                mma16816(c[j],   ah, bh[0], bh[1]);
                mma16816(c[j],   al, bh[0], bh[1]);
                mma16816(c[j+1], ah, bh[2], bh[3]);
                mma16816(c[j+1], al, bh[2], bh[3]);
                if (P3) {
                    uint32_t bl[4];
                    if (TB) ldsm_x4t(bl, v_addr2(st + G_SB_L, ks, j, lane));
                    else    ldsm_x4 (bl, b_addr2(st + G_SB_L, j, ks, lane));
                    mma16816(c[j],   ah, bl[0], bl[1]);
                    mma16816(c[j+1], ah, bl[2], bl[3]);
                }
            }
        }
        __syncthreads();
    }
}

// ---------------------------------------------------------------------------
// Kernel 1: Q projection (3-pass — anchors logit argmax). grid (NN/128, NH, NB)
// ---------------------------------------------------------------------------
__global__ void __launch_bounds__(256, 2)
q_proj_kernel() {
    int b = blockIdx.z, h = blockIdx.y, n0 = blockIdx.x * 128;
    float c[8][4] = {};
    gemm128x64<true, true>(g_Xh + (size_t)(b*NN + n0)*ND, g_Xl + (size_t)(b*NN + n0)*ND, ND,
                           g_Pqh + (size_t)h*ND*NK, g_Pql + (size_t)h*ND*NK, NK,
                           (size_t)64*NK, ND/64, c);
    int lane = threadIdx.x & 31, w = threadIdx.x >> 5;
    int gid = lane >> 2, t4 = lane & 3;
    int grow0 = n0 + w*16 + gid;
    size_t r0 = ((size_t)(b*NH + h)*NN + grow0)*NK;
#pragma unroll
    for (int j = 0; j < 8; j++) {
        int col = 8*j + 2*t4;
        split2(c[j][0], c[j][1], &g_Qh[r0 + col], &g_Ql[r0 + col]);
        split2(c[j][2], c[j][3], &g_Qh[r0 + 8*NK + col], &g_Ql[r0 + 8*NK + col]);
    }
}

// ---------------------------------------------------------------------------
// Kernel 2: K/V projection. grid (NM/128, 2(sel), NB).
// K: 3-pass (logit precision). V: 2-pass (only V-hi is consumed downstream).
// ---------------------------------------------------------------------------
__global__ void __launch_bounds__(256, 2)
kv_proj_kernel() {
    int b = blockIdx.z, sel = blockIdx.y, m0 = blockIdx.x * 128;
    float c[8][4] = {};
    const __half* Ah = g_Mh + (size_t)(b*NM + m0)*ND;
    const __half* Al = g_Ml + (size_t)(b*NM + m0)*ND;
    if (sel == 0)
        gemm128x64<true, true >(Ah, Al, ND, g_Pkh, g_Pkl, NK, (size_t)64*NK, ND/64, c);
    else
        gemm128x64<true, false>(Ah, Al, ND, g_Pvh, g_Pvl, NK, (size_t)64*NK, ND/64, c);

    int lane = threadIdx.x & 31, w = threadIdx.x >> 5;
    int gid = lane >> 2, t4 = lane & 3;
    int grow0 = m0 + w*16 + gid;
    size_t r0 = (size_t)(b*NM + grow0)*NK;
    if (sel == 0) {
#pragma unroll
        for (int j = 0; j < 8; j++) {
            int col = 8*j + 2*t4;
            split2(c[j][0], c[j][1], &g_Kh[r0 + col], &g_Kl[r0 + col]);
            split2(c[j][2], c[j][3], &g_Kh[r0 + 8*NK + col], &g_Kl[r0 + 8*NK + col]);
        }
    } else {
#pragma unroll
        for (int j = 0; j < 8; j++) {
            int col = 8*j + 2*t4;
            *(__half2*)&g_Vh[r0 + col] =
                __halves2half2(__float2half_rn(c[j][0]), __float2half_rn(c[j][1]));
            *(__half2*)&g_Vh[r0 + 8*NK + col] =
                __halves2half2(__float2half_rn(c[j][2]), __float2half_rn(c[j][3]));
        }
    }
}

// ---------------------------------------------------------------------------
// Kernel 3: mma.sync flash attention — EXACT round-10 structure (measured
// best): 2-stage cp.async, cp.async issued in previous compute window, two
// barriers/iter, mask added AFTER the S-MMA block, PF_L2 mask prefetch,
// V-hi-only PV. Stage (24KB): KH 0, KL 8K, VH 16K. Q at 48K/64K. 80KB.
// ---------------------------------------------------------------------------
#define AST    24576
#define A_KH   0
#define A_KL   8192
#define A_VH   16384
#define S_QH   49152
#define S_QL   65536
#define SMEM_ATT 81920
#define L2E 1.4426950408889634f

__global__ void __launch_bounds__(256, 2)
attn_kernel(const float* __restrict__ mask) {
    extern __shared__ char smem[];
    const uint32_t sb = smem_u32(smem);
    const int tid = threadIdx.x;
    const int w = tid >> 5, lane = tid & 31;
    const int gid = lane >> 2, t4 = lane & 3;
    const int wrow0 = w * 16;
    const int b = blockIdx.z, h = blockIdx.y, n0 = blockIdx.x * 128;

    const __half* kh_g = g_Kh + (size_t)b*NM*NK;
    const __half* kl_g = g_Kl + (size_t)b*NM*NK;
    const __half* vh_g = g_Vh + (size_t)b*NM*NV;

    // per-lane mask prefetch pointer: 32 lanes cover this warp's 16 rows x 64 cols
    const float* pfb = mask + ((size_t)(b*NH + h)*NN + n0 + wrow0 + (lane >> 1))*(size_t)NM
                            + (lane & 1) * 32;

    {
        load_f16_tile_cp(sb + A_KH, kh_g, NK, 64);
        load_f16_tile_cp(sb + A_KL, kl_g, NK, 64);
        load_f16_tile_cp(sb + A_VH, vh_g, NV, 64);
        CP_COMMIT();
        PF_L2(pfb);                       // iter-0 mask into L2
    }
    size_t qoff = ((size_t)(b*NH + h)*NN + n0) * NK;
    load_f16_tile((char*)smem + S_QH, g_Qh + qoff, NK, 128);
    load_f16_tile((char*)smem + S_QL, g_Ql + qoff, NK, 128);
    __syncthreads();

    uint32_t qh[4][4];
#pragma unroll
    for (int ks = 0; ks < 4; ks++) ldsm_x4(qh[ks], a_addr(sb + S_QH, wrow0, ks, lane));

    float o[8][4];
#pragma unroll
    for (int j = 0; j < 8; j++) { o[j][0]=0.f; o[j][1]=0.f; o[j][2]=0.f; o[j][3]=0.f; }
    float gmax0 = -1e30f, gmax1 = -1e30f, gs0 = 0.f, gs1 = 0.f;

    const int grow0 = n0 + wrow0 + gid;
    const float* mp0 = mask + (((size_t)(b*NH + h)*NN + grow0))*(size_t)NM + 2*t4;
    const float* mp1 = mp0 + (size_t)8 * NM;

    const int NIT = NM / 64;
    for (int it = 0; it < NIT; it++) {
        const int m0 = it * 64;
        if (it + 1 < NIT) {
            uint32_t st = sb + ((it + 1) & 1) * AST;
            const int m1 = m0 + 64;
            load_f16_tile_cp(st + A_KH, kh_g + (size_t)m1*NK, NK, 64);
            load_f16_tile_cp(st + A_KL, kl_g + (size_t)m1*NK, NK, 64);
            load_f16_tile_cp(st + A_VH, vh_g + (size_t)m1*NV, NV, 64);
            CP_COMMIT();
            PF_L2(pfb + m1);              // next iter's mask into L2
            CP_WAIT1();
        } else {
            CP_WAIT0();
        }
        __syncthreads();
        const uint32_t st = sb + (it & 1) * AST;

        float c[8][4];
#pragma unroll
        for (int j = 0; j < 8; j++) { c[j][0]=0.f; c[j][1]=0.f; c[j][2]=0.f; c[j][3]=0.f; }
#pragma unroll
        for (int ks = 0; ks < 4; ks++) {
            uint32_t ql[4];
            ldsm_x4(ql, a_addr(sb + S_QL, wrow0, ks, lane));
#pragma unroll
            for (int j = 0; j < 8; j += 2) {
                uint32_t bh[4], bl[4];
                ldsm_x4(bh, b_addr2(st + A_KH, j, ks, lane));
                ldsm_x4(bl, b_addr2(st + A_KL, j, ks, lane));
                mma16816(c[j],   qh[ks], bh[0], bh[1]);
                mma16816(c[j],   ql,     bh[0], bh[1]);
                mma16816(c[j],   qh[ks], bl[0], bl[1]);
                mma16816(c[j+1], qh[ks], bh[2], bh[3]);
                mma16816(c[j+1], ql,     bh[2], bh[3]);
                mma16816(c[j+1], qh[ks], bl[2], bl[3]);
            }
        }

        float mx0 = -1e30f, mx1 = -1e30f;
#pragma unroll
        for (int j = 0; j < 8; j++) {
            float2 a = *(const float2*)(mp0 + m0 + 8*j);
            float2 d = *(const float2*)(mp1 + m0 + 8*j);
            c[j][0] += a.x; c[j][1] += a.y; c[j][2] += d.x; c[j][3] += d.y;
            mx0 = fmaxf(mx0, fmaxf(c[j][0], c[j][1]));
            mx1 = fmaxf(mx1, fmaxf(c[j][2], c[j][3]));
        }
        mx0 = fmaxf(mx0, __shfl_xor_sync(0xffffffffu, mx0, 1));
        mx0 = fmaxf(mx0, __shfl_xor_sync(0xffffffffu, mx0, 2));
        mx1 = fmaxf(mx1, __shfl_xor_sync(0xffffffffu, mx1, 1));
        mx1 = fmaxf(mx1, __shfl_xor_sync(0xffffffffu, mx1, 2));

        float mn0 = fmaxf(gmax0, mx0), mn1 = fmaxf(gmax1, mx1);
        float sc0 = __expf(gmax0 - mn0), sc1 = __expf(gmax1 - mn1);
        gmax0 = mn0; gmax1 = mn1;

        uint32_t pk[8][2];
        float rs0 = 0.f, rs1 = 0.f;
#pragma unroll
        for (int j = 0; j < 8; j++) {
            __half2 t0 = __floats2half2_rn((c[j][0]-mn0)*L2E, (c[j][1]-mn0)*L2E);
            __half2 t1 = __floats2half2_rn((c[j][2]-mn1)*L2E, (c[j][3]-mn1)*L2E);
            pk[j][0] = ex2_h2(*(uint32_t*)&t0);
            pk[j][1] = ex2_h2(*(uint32_t*)&t1);
            float2 f0 = __half22float2(*(__half2*)&pk[j][0]);
            float2 f1 = __half22float2(*(__half2*)&pk[j][1]);
            rs0 += f0.x + f0.y; rs1 += f1.x + f1.y;
        }
        rs0 += __shfl_xor_sync(0xffffffffu, rs0, 1);
        rs0 += __shfl_xor_sync(0xffffffffu, rs0, 2);
        rs1 += __shfl_xor_sync(0xffffffffu, rs1, 1);
        rs1 += __shfl_xor_sync(0xffffffffu, rs1, 2);
        gs0 = gs0 * sc0 + rs0;
        gs1 = gs1 * sc1 + rs1;

#pragma unroll
        for (int j = 0; j < 8; j++) {
            o[j][0] *= sc0; o[j][1] *= sc0; o[j][2] *= sc1; o[j][3] *= sc1;
        }
#pragma unroll
        for (int ks = 0; ks < 4; ks++) {
            uint32_t pa[4] = { pk[2*ks][0], pk[2*ks][1], pk[2*ks+1][0], pk[2*ks+1][1] };
#pragma unroll
            for (int jv = 0; jv < 8; jv += 2) {
                uint32_t vh[4];
                ldsm_x4t(vh, v_addr2(st + A_VH, ks, jv, lane));
                mma16816(o[jv],   pa, vh[0], vh[1]);
                mma16816(o[jv+1], pa, vh[2], vh[3]);
            }
        }
        __syncthreads();
    }

    // epilogue: normalize, split-store O as fp16 hi/lo [b][n][h][v]
    float inv0 = 1.0f / gs0, inv1 = 1.0f / gs1;
    size_t o0 = ((size_t)(b*NN + grow0)*NH + h)*NV + 2*t4;
    size_t o1 = ((size_t)(b*NN + grow0 + 8)*NH + h)*NV + 2*t4;
#pragma unroll
    for (int jv = 0; jv < 8; jv++) {
        split2(o[jv][0]*inv0, o[jv][1]*inv0, &g_Oh[o0 + 8*jv], &g_Ol[o0 + 8*jv]);
        split2(o[jv][2]*inv1, o[jv][3]*inv1, &g_Oh[o1 + 8*jv], &g_Ol[o1 + 8*jv]);
    }
}

// ---------------------------------------------------------------------------
// Kernel 4: output projection, 2-pass (Po-lo dropped). grid (ND/64, NN/128, NB).
// ---------------------------------------------------------------------------
__global__ void __launch_bounds__(256, 2)
out_proj_kernel(float* __restrict__ Y) {
    int b = blockIdx.z, n0 = blockIdx.y * 128, d0 = blockIdx.x * 64;
    float c[8][4] = {};
    gemm128x64<false, false>(g_Oh + (size_t)(b*NN + n0)*(NH*NV),
                             g_Ol + (size_t)(b*NN + n0)*(NH*NV), NH*NV,
                             g_Poh + (size_t)d0*NV, g_Pol + (size_t)d0*NV, NV,
                             (size_t)ND*NV, NH, c);
    int lane = threadIdx.x & 31, w = threadIdx.x >> 5;
    int gid = lane >> 2, t4 = lane & 3;
    int grow0 = n0 + w*16 + gid;
    size_t r0 = (size_t)(b*NN + grow0)*ND + d0;
#pragma unroll
    for (int j = 0; j < 8; j++) {
        int col = 8*j + 2*t4;
        *(float2*)&Y[r0 + col]        = make_float2(c[j][0], c[j][1]);
        *(float2*)&Y[r0 + 8*ND + col] = make_float2(c[j][2], c[j][3]);
    }
}

// ---------------------------------------------------------------------------
extern "C" void kernel_launch(void* const* d_in, const int* in_sizes, int n_in,
                              void* d_out, int out_size) {
    const float* X    = (const float*)d_in[0];
    const float* Mi   = (const float*)d_in[1];
    const float* mask = (const float*)d_in[2];
    const float* Pq   = (const float*)d_in[3];
    const float* Pk   = (const float*)d_in[4];
    const float* Pv   = (const float*)d_in[5];
    const float* Po   = (const float*)d_in[6];
    float* Y = (float*)d_out;

    cudaFuncSetAttribute(q_proj_kernel,   cudaFuncAttributeMaxDynamicSharedMemorySize, SMEM_G);
    cudaFuncSetAttribute(kv_proj_kernel,  cudaFuncAttributeMaxDynamicSharedMemorySize, SMEM_G);
    cudaFuncSetAttribute(attn_kernel,     cudaFuncAttributeMaxDynamicSharedMemorySize, SMEM_ATT);
    cudaFuncSetAttribute(out_proj_kernel, cudaFuncAttributeMaxDynamicSharedMemorySize, SMEM_G);

    split_all_kernel<<<dim3(2048, 6), 256>>>(X, Mi, Pq, Pk, Pv, Po);

    kv_proj_kernel<<<dim3(NM/128, 2, NB), 256, SMEM_G>>>();
    q_proj_kernel<<<dim3(NN/128, NH, NB), 256, SMEM_G>>>();
    attn_kernel<<<dim3(NN/128, NH, NB), 256, SMEM_ATT>>>(mask);
    out_proj_kernel<<<dim3(ND/64, NN/128, NB), 256, SMEM_G>>>(Y);
}

// round 14
// speedup vs baseline: 1.1259x; 1.0182x over previous
#include <cuda_runtime.h>
#include <cuda_fp16.h>
#include <cstdint>

#define NB 2
#define NN 2048
#define NM 2048
#define ND 1024
#define NH 16
#define NK 64
#define NV 64

// ---------------- scratch (__device__ globals; no allocs allowed) ----------
__device__ __half g_Xh[(size_t)NB*NN*ND],   g_Xl[(size_t)NB*NN*ND];
__device__ __half g_Mh[(size_t)NB*NM*ND],   g_Ml[(size_t)NB*NM*ND];
__device__ __half g_Pqh[(size_t)NH*ND*NK],  g_Pql[(size_t)NH*ND*NK];
__device__ __half g_Pkh[(size_t)ND*NK],     g_Pkl[(size_t)ND*NK];
__device__ __half g_Pvh[(size_t)ND*NV],     g_Pvl[(size_t)ND*NV];
__device__ __half g_Poh[(size_t)NH*ND*NV],  g_Pol[(size_t)NH*ND*NV];
__device__ __half g_Qh[(size_t)NB*NH*NN*NK], g_Ql[(size_t)NB*NH*NN*NK];
__device__ __half g_Kh[(size_t)NB*NM*NK],   g_Kl[(size_t)NB*NM*NK];
__device__ __half g_Vh[(size_t)NB*NM*NV];
__device__ __half g_Oh[(size_t)NB*NN*NH*NV], g_Ol[(size_t)NB*NN*NH*NV];

// ---------------- helpers --------------------------------------------------
__device__ __forceinline__ uint32_t smem_u32(const void* p) {
    uint32_t a;
    asm("{ .reg .u64 t; cvta.to.shared.u64 t, %1; cvt.u32.u64 %0, t; }" : "=r"(a) : "l"(p));
    return a;
}
__device__ __forceinline__ void ldsm_x4(uint32_t (&r)[4], uint32_t a) {
    asm volatile("ldmatrix.sync.aligned.m8n8.x4.shared.b16 {%0,%1,%2,%3}, [%4];"
                 : "=r"(r[0]), "=r"(r[1]), "=r"(r[2]), "=r"(r[3]) : "r"(a));
}
__device__ __forceinline__ void ldsm_x4t(uint32_t (&r)[4], uint32_t a) {
    asm volatile("ldmatrix.sync.aligned.m8n8.x4.trans.shared.b16 {%0,%1,%2,%3}, [%4];"
                 : "=r"(r[0]), "=r"(r[1]), "=r"(r[2]), "=r"(r[3]) : "r"(a));
}
__device__ __forceinline__ void mma16816(float (&c)[4], const uint32_t (&a)[4],
                                         uint32_t b0, uint32_t b1) {
    asm volatile("mma.sync.aligned.m16n8k16.row.col.f32.f16.f16.f32 "
                 "{%0,%1,%2,%3}, {%4,%5,%6,%7}, {%8,%9}, {%0,%1,%2,%3};"
                 : "+f"(c[0]), "+f"(c[1]), "+f"(c[2]), "+f"(c[3])
                 : "r"(a[0]), "r"(a[1]), "r"(a[2]), "r"(a[3]), "r"(b0), "r"(b1));
}
__device__ __forceinline__ uint32_t ex2_h2(uint32_t x) {
    uint32_t r;
    asm volatile("ex2.approx.f16x2 %0, %1;" : "=r"(r) : "r"(x));
    return r;
}
__device__ __forceinline__ void split2(float a, float b, __half* hp, __half* lp) {
    __half h0 = __float2half_rn(a), h1 = __float2half_rn(b);
    *(__half2*)hp = __halves2half2(h0, h1);
    *(__half2*)lp = __halves2half2(__float2half_rn(a - __half2float(h0)),
                                   __float2half_rn(b - __half2float(h1)));
}
#define CP_COMMIT() asm volatile("cp.async.commit_group;" ::: "memory")
#define CP_WAIT1()  asm volatile("cp.async.wait_group 1;" ::: "memory")
#define CP_WAIT0()  asm volatile("cp.async.wait_group 0;" ::: "memory")
#define PF_L2(p)    asm volatile("prefetch.global.L2 [%0];" :: "l"(p))

// swizzled 128B-row f16 tile loader (64 halves per row) — sync version
__device__ __forceinline__ void load_f16_tile(char* s, const __half* g,
                                              int gstride, int rows) {
    for (int i = threadIdx.x; i < rows * 8; i += 256) {
        int row = i >> 3, c = i & 7;
        uint4 v = *(const uint4*)(g + (size_t)row * gstride + c * 8);
        int off = row * 128 + c * 16;
        *(uint4*)(s + (off ^ ((off >> 3) & 0x70))) = v;
    }
}
// cp.async version
__device__ __forceinline__ void load_f16_tile_cp(uint32_t sbase, const __half* g,
                                                 int gstride, int rows) {
    for (int i = threadIdx.x; i < rows * 8; i += 256) {
        int row = i >> 3, c = i & 7;
        int off = row * 128 + c * 16;
        asm volatile("cp.async.cg.shared.global [%0], [%1], 16;"
                     :: "r"(sbase + (off ^ ((off >> 3) & 0x70))),
                        "l"(g + (size_t)row * gstride + c * 8) : "memory");
    }
}
// fragment address helpers (swizzle folded)
__device__ __forceinline__ uint32_t a_addr(uint32_t base, int row0, int ks, int lane) {
    int m = lane >> 3;
    int r = row0 + ((m & 1) << 3) + (lane & 7);
    int cb = ((((m >> 1) << 3) + (ks << 4)) << 1);
    return base + r * 128 + (cb ^ ((r & 7) << 4));
}
// x4 pair: lanes 0-15 -> fragment j, lanes 16-31 -> fragment j+1 (B in [n][k])
__device__ __forceinline__ uint32_t b_addr2(uint32_t base, int j, int ks, int lane) {
    int jj = j + (lane >> 4);
    int l = lane & 15;
    int r = (jj << 3) + (l & 7);
    int cb = (((ks << 4) + ((l >> 3) << 3)) << 1);
    return base + r * 128 + (cb ^ ((l & 7) << 4));
}
// x4 trans pair: lanes 0-15 -> jv, lanes 16-31 -> jv+1 (B in [k][n])
__device__ __forceinline__ uint32_t v_addr2(uint32_t base, int ks, int jv, int lane) {
    int jj = jv + (lane >> 4);
    int l = lane & 15;
    int r = (ks << 4) + l;
    int cb = (jj << 4);
    return base + r * 128 + (cb ^ ((l & 7) << 4));
}

// ---------------------------------------------------------------------------
// Kernel 0: fp32 -> fp16 hi/lo split, ALL tensors in one launch (grid.y = tensor)
// ---------------------------------------------------------------------------
__global__ void split_all_kernel(const float* __restrict__ X, const float* __restrict__ Mi,
                                 const float* __restrict__ Pq, const float* __restrict__ Pk,
                                 const float* __restrict__ Pv, const float* __restrict__ Po) {
    const float* s; __half* hp; __half* lp; size_t n;
    switch (blockIdx.y) {
        case 0: s = X;  hp = g_Xh;  lp = g_Xl;  n = (size_t)NB*NN*ND; break;
        case 1: s = Mi; hp = g_Mh;  lp = g_Ml;  n = (size_t)NB*NM*ND; break;
        case 2: s = Pq; hp = g_Pqh; lp = g_Pql; n = (size_t)NH*ND*NK; break;
        case 3: s = Pk; hp = g_Pkh; lp = g_Pkl; n = (size_t)ND*NK;    break;
        case 4: s = Pv; hp = g_Pvh; lp = g_Pvl; n = (size_t)ND*NV;    break;
        default:s = Po; hp = g_Poh; lp = g_Pol; n = (size_t)NH*ND*NV; break;
    }
    int n4 = (int)(n / 4);
    for (int i = blockIdx.x * blockDim.x + threadIdx.x; i < n4;
         i += gridDim.x * blockDim.x) {
        float4 v = ((const float4*)s)[i];
        split2(v.x, v.y, hp + 4*i,     lp + 4*i);
        split2(v.z, v.w, hp + 4*i + 2, lp + 4*i + 2);
    }
}

// ---------------------------------------------------------------------------
// Shared HMMA core, 2-stage cp.async pipeline, batch-loaded K fragments +
// pass-separated MMA scheduling (8 independent accumulator chains per pass).
// ---------------------------------------------------------------------------
#define GST    49152
#define G_SA_H 0
#define G_SA_L 16384
#define G_SB_H 32768
#define G_SB_L 40960
#define SMEM_G 98304

template <bool TB, bool P3>
__device__ __forceinline__ void gemm128x64(const __half* Ah, const __half* Al, int lda,
                                           const __half* Bh, const __half* Bl, int ldb,
                                           size_t bstep, int nchunks, float (&c)[8][4]) {
    extern __shared__ char smem[];
    uint32_t sb = smem_u32(smem);
    int lane = threadIdx.x & 31, w = threadIdx.x >> 5, wrow0 = w * 16;

    {
        uint32_t st = sb;
        load_f16_tile_cp(st + G_SA_H, Ah, lda, 128);
        load_f16_tile_cp(st + G_SA_L, Al, lda, 128);
        load_f16_tile_cp(st + G_SB_H, Bh, ldb, 64);
        if (P3) load_f16_tile_cp(st + G_SB_L, Bl, ldb, 64);
        CP_COMMIT();
    }
    for (int ch = 0; ch < nchunks; ch++) {
        if (ch + 1 < nchunks) {
            uint32_t st = sb + ((ch + 1) & 1) * GST;
            load_f16_tile_cp(st + G_SA_H, Ah + (ch + 1) * 64, lda, 128);
            load_f16_tile_cp(st + G_SA_L, Al + (ch + 1) * 64, lda, 128);
            load_f16_tile_cp(st + G_SB_H, Bh + (ch + 1) * bstep, ldb, 64);
            if (P3) load_f16_tile_cp(st + G_SB_L, Bl + (ch + 1) * bstep, ldb, 64);
            CP_COMMIT();
            CP_WAIT1();
        } else {
            CP_WAIT0();
        }
        __syncthreads();
        uint32_t st = sb + (ch & 1) * GST;
#pragma unroll
        for (int ks = 0; ks < 4; ks++) {
            uint32_t ah[4], al[4];
            ldsm_x4(ah, a_addr(st + G_SA_H, wrow0, ks, lane));
            ldsm_x4(al, a_addr(st + G_SA_L, wrow0, ks, lane));
            // batch-load all B-hi fragments (4 pairs)
            uint32_t bh[4][4];
#pragma unroll
            for (int jp = 0; jp < 4; jp++) {
                if (TB) ldsm_x4t(bh[jp], v_addr2(st + G_SB_H, ks, 2*jp, lane));
                else    ldsm_x4 (bh[jp], b_addr2(st + G_SB_H, 2*jp, ks, lane));
            }
            // pass 1: ah*bh (8 independent chains)
#pragma unroll
            for (int jp = 0; jp < 4; jp++) {
                mma16816(c[2*jp],   ah, bh[jp][0], bh[jp][1]);
                mma16816(c[2*jp+1], ah, bh[jp][2], bh[jp][3]);
            }
            // pass 2: al*bh
#pragma unroll
            for (int jp = 0; jp < 4; jp++) {
                mma16816(c[2*jp],   al, bh[jp][0], bh[jp][1]);
                mma16816(c[2*jp+1], al, bh[jp][2], bh[jp][3]);
            }
            if (P3) {
                uint32_t bl[4][4];
#pragma unroll
                for (int jp = 0; jp < 4; jp++) {
                    if (TB) ldsm_x4t(bl[jp], v_addr2(st + G_SB_L, ks, 2*jp, lane));
                    else    ldsm_x4 (bl[jp], b_addr2(st + G_SB_L, 2*jp, ks, lane));
                }
#pragma unroll
                for (int jp = 0; jp < 4; jp++) {
                    mma16816(c[2*jp],   ah, bl[jp][0], bl[jp][1]);
                    mma16816(c[2*jp+1], ah, bl[jp][2], bl[jp][3]);
                }
            }
        }
        __syncthreads();
    }
}

// ---------------------------------------------------------------------------
// Kernel 1: Q projection (3-pass — anchors logit argmax). grid (NN/128, NH, NB)
// ---------------------------------------------------------------------------
__global__ void __launch_bounds__(256, 2)
q_proj_kernel() {
    int b = blockIdx.z, h = blockIdx.y, n0 = blockIdx.x * 128;
    float c[8][4] = {};
    gemm128x64<true, true>(g_Xh + (size_t)(b*NN + n0)*ND, g_Xl + (size_t)(b*NN + n0)*ND, ND,
                           g_Pqh + (size_t)h*ND*NK, g_Pql + (size_t)h*ND*NK, NK,
                           (size_t)64*NK, ND/64, c);
    int lane = threadIdx.x & 31, w = threadIdx.x >> 5;
    int gid = lane >> 2, t4 = lane & 3;
    int grow0 = n0 + w*16 + gid;
    size_t r0 = ((size_t)(b*NH + h)*NN + grow0)*NK;
#pragma unroll
    for (int j = 0; j < 8; j++) {
        int col = 8*j + 2*t4;
        split2(c[j][0], c[j][1], &g_Qh[r0 + col], &g_Ql[r0 + col]);
        split2(c[j][2], c[j][3], &g_Qh[r0 + 8*NK + col], &g_Ql[r0 + 8*NK + col]);
    }
}

// ---------------------------------------------------------------------------
// Kernel 2: K/V projection. grid (NM/128, 2(sel), NB).
// K: 3-pass (logit precision). V: 2-pass (only V-hi is consumed downstream).
// ---------------------------------------------------------------------------
__global__ void __launch_bounds__(256, 2)
kv_proj_kernel() {
    int b = blockIdx.z, sel = blockIdx.y, m0 = blockIdx.x * 128;
    float c[8][4] = {};
    const __half* Ah = g_Mh + (size_t)(b*NM + m0)*ND;
    const __half* Al = g_Ml + (size_t)(b*NM + m0)*ND;
    if (sel == 0)
        gemm128x64<true, true >(Ah, Al, ND, g_Pkh, g_Pkl, NK, (size_t)64*NK, ND/64, c);
    else
        gemm128x64<true, false>(Ah, Al, ND, g_Pvh, g_Pvl, NK, (size_t)64*NK, ND/64, c);

    int lane = threadIdx.x & 31, w = threadIdx.x >> 5;
    int gid = lane >> 2, t4 = lane & 3;
    int grow0 = m0 + w*16 + gid;
    size_t r0 = (size_t)(b*NM + grow0)*NK;
    if (sel == 0) {
#pragma unroll
        for (int j = 0; j < 8; j++) {
            int col = 8*j + 2*t4;
            split2(c[j][0], c[j][1], &g_Kh[r0 + col], &g_Kl[r0 + col]);
            split2(c[j][2], c[j][3], &g_Kh[r0 + 8*NK + col], &g_Kl[r0 + 8*NK + col]);
        }
    } else {
#pragma unroll
        for (int j = 0; j < 8; j++) {
            int col = 8*j + 2*t4;
            *(__half2*)&g_Vh[r0 + col] =
                __halves2half2(__float2half_rn(c[j][0]), __float2half_rn(c[j][1]));
            *(__half2*)&g_Vh[r0 + 8*NK + col] =
                __halves2half2(__float2half_rn(c[j][2]), __float2half_rn(c[j][3]));
        }
    }
}

// ---------------------------------------------------------------------------
// Kernel 3: mma.sync flash attention — round-10 pipeline + pass-separated
// S-MMA scheduling (batch K-fragment loads, 8 independent chains per pass).
// Stage (24KB): KH 0, KL 8K, VH 16K. Q at 48K/64K. 80KB.
// ---------------------------------------------------------------------------
#define AST    24576
#define A_KH   0
#define A_KL   8192
#define A_VH   16384
#define S_QH   49152
#define S_QL   65536
#define SMEM_ATT 81920
#define L2E 1.4426950408889634f

__global__ void __launch_bounds__(256, 2)
attn_kernel(const float* __restrict__ mask) {
    extern __shared__ char smem[];
    const uint32_t sb = smem_u32(smem);
    const int tid = threadIdx.x;
    const int w = tid >> 5, lane = tid & 31;
    const int gid = lane >> 2, t4 = lane & 3;
    const int wrow0 = w * 16;
    const int b = blockIdx.z, h = blockIdx.y, n0 = blockIdx.x * 128;

    const __half* kh_g = g_Kh + (size_t)b*NM*NK;
    const __half* kl_g = g_Kl + (size_t)b*NM*NK;
    const __half* vh_g = g_Vh + (size_t)b*NM*NV;

    const float* pfb = mask + ((size_t)(b*NH + h)*NN + n0 + wrow0 + (lane >> 1))*(size_t)NM
                            + (lane & 1) * 32;

    {
        load_f16_tile_cp(sb + A_KH, kh_g, NK, 64);
        load_f16_tile_cp(sb + A_KL, kl_g, NK, 64);
        load_f16_tile_cp(sb + A_VH, vh_g, NV, 64);
        CP_COMMIT();
        PF_L2(pfb);
    }
    size_t qoff = ((size_t)(b*NH + h)*NN + n0) * NK;
    load_f16_tile((char*)smem + S_QH, g_Qh + qoff, NK, 128);
    load_f16_tile((char*)smem + S_QL, g_Ql + qoff, NK, 128);
    __syncthreads();

    uint32_t qh[4][4];
#pragma unroll
    for (int ks = 0; ks < 4; ks++) ldsm_x4(qh[ks], a_addr(sb + S_QH, wrow0, ks, lane));

    float o[8][4];
#pragma unroll
    for (int j = 0; j < 8; j++) { o[j][0]=0.f; o[j][1]=0.f; o[j][2]=0.f; o[j][3]=0.f; }
    float gmax0 = -1e30f, gmax1 = -1e30f, gs0 = 0.f, gs1 = 0.f;

    const int grow0 = n0 + wrow0 + gid;
    const float* mp0 = mask + (((size_t)(b*NH + h)*NN + grow0))*(size_t)NM + 2*t4;
    const float* mp1 = mp0 + (size_t)8 * NM;

    const int NIT = NM / 64;
    for (int it = 0; it < NIT; it++) {
        const int m0 = it * 64;
        if (it + 1 < NIT) {
            uint32_t st = sb + ((it + 1) & 1) * AST;
            const int m1 = m0 + 64;
            load_f16_tile_cp(st + A_KH, kh_g + (size_t)m1*NK, NK, 64);
            load_f16_tile_cp(st + A_KL, kl_g + (size_t)m1*NK, NK, 64);
            load_f16_tile_cp(st + A_VH, vh_g + (size_t)m1*NV, NV, 64);
            CP_COMMIT();
            PF_L2(pfb + m1);
            CP_WAIT1();
        } else {
            CP_WAIT0();
        }
        __syncthreads();
        const uint32_t st = sb + (it & 1) * AST;

        float c[8][4];
#pragma unroll
        for (int j = 0; j < 8; j++) { c[j][0]=0.f; c[j][1]=0.f; c[j][2]=0.f; c[j][3]=0.f; }
#pragma unroll
        for (int ks = 0; ks < 4; ks++) {
            uint32_t ql[4];
            ldsm_x4(ql, a_addr(sb + S_QL, wrow0, ks, lane));
            // batch-load all K-hi / K-lo fragments for this k-step
            uint32_t bh[4][4], bl[4][4];
#pragma unroll
            for (int jp = 0; jp < 4; jp++)
                ldsm_x4(bh[jp], b_addr2(st + A_KH, 2*jp, ks, lane));
#pragma unroll
            for (int jp = 0; jp < 4; jp++)
                ldsm_x4(bl[jp], b_addr2(st + A_KL, 2*jp, ks, lane));
            // pass 1: qh*Kh — 8 independent accumulator chains
#pragma unroll
            for (int jp = 0; jp < 4; jp++) {
                mma16816(c[2*jp],   qh[ks], bh[jp][0], bh[jp][1]);
                mma16816(c[2*jp+1], qh[ks], bh[jp][2], bh[jp][3]);
            }
            // pass 2: ql*Kh
#pragma unroll
            for (int jp = 0; jp < 4; jp++) {
                mma16816(c[2*jp],   ql, bh[jp][0], bh[jp][1]);
                mma16816(c[2*jp+1], ql, bh[jp][2], bh[jp][3]);
            }
            // pass 3: qh*Kl
#pragma unroll
            for (int jp = 0; jp < 4; jp++) {
                mma16816(c[2*jp],   qh[ks], bl[jp][0], bl[jp][1]);
                mma16816(c[2*jp+1], qh[ks], bl[jp][2], bl[jp][3]);
            }
        }

        float mx0 = -1e30f, mx1 = -1e30f;
#pragma unroll
        for (int j = 0; j < 8; j++) {
            float2 a = *(const float2*)(mp0 + m0 + 8*j);
            float2 d = *(const float2*)(mp1 + m0 + 8*j);
            c[j][0] += a.x; c[j][1] += a.y; c[j][2] += d.x; c[j][3] += d.y;
            mx0 = fmaxf(mx0, fmaxf(c[j][0], c[j][1]));
            mx1 = fmaxf(mx1, fmaxf(c[j][2], c[j][3]));
        }
        mx0 = fmaxf(mx0, __shfl_xor_sync(0xffffffffu, mx0, 1));
        mx0 = fmaxf(mx0, __shfl_xor_sync(0xffffffffu, mx0, 2));
        mx1 = fmaxf(mx1, __shfl_xor_sync(0xffffffffu, mx1, 1));
        mx1 = fmaxf(mx1, __shfl_xor_sync(0xffffffffu, mx1, 2));

        float mn0 = fmaxf(gmax0, mx0), mn1 = fmaxf(gmax1, mx1);
        float sc0 = __expf(gmax0 - mn0), sc1 = __expf(gmax1 - mn1);
        gmax0 = mn0; gmax1 = mn1;

        uint32_t pk[8][2];
        float rs0 = 0.f, rs1 = 0.f;
#pragma unroll
        for (int j = 0; j < 8; j++) {
            __half2 t0 = __floats2half2_rn((c[j][0]-mn0)*L2E, (c[j][1]-mn0)*L2E);
            __half2 t1 = __floats2half2_rn((c[j][2]-mn1)*L2E, (c[j][3]-mn1)*L2E);
            pk[j][0] = ex2_h2(*(uint32_t*)&t0);
            pk[j][1] = ex2_h2(*(uint32_t*)&t1);
            float2 f0 = __half22float2(*(__half2*)&pk[j][0]);
            float2 f1 = __half22float2(*(__half2*)&pk[j][1]);
            rs0 += f0.x + f0.y; rs1 += f1.x + f1.y;
        }
        rs0 += __shfl_xor_sync(0xffffffffu, rs0, 1);
        rs0 += __shfl_xor_sync(0xffffffffu, rs0, 2);
        rs1 += __shfl_xor_sync(0xffffffffu, rs1, 1);
        rs1 += __shfl_xor_sync(0xffffffffu, rs1, 2);
        gs0 = gs0 * sc0 + rs0;
        gs1 = gs1 * sc1 + rs1;

#pragma unroll
        for (int j = 0; j < 8; j++) {
            o[j][0] *= sc0; o[j][1] *= sc0; o[j][2] *= sc1; o[j][3] *= sc1;
        }
#pragma unroll
        for (int ks = 0; ks < 4; ks++) {
            uint32_t pa[4] = { pk[2*ks][0], pk[2*ks][1], pk[2*ks+1][0], pk[2*ks+1][1] };
#pragma unroll
            for (int jv = 0; jv < 8; jv += 2) {
                uint32_t vh[4];
                ldsm_x4t(vh, v_addr2(st + A_VH, ks, jv, lane));
                mma16816(o[jv],   pa, vh[0], vh[1]);
                mma16816(o[jv+1], pa, vh[2], vh[3]);
            }
        }
        __syncthreads();
    }

    // epilogue: normalize, split-store O as fp16 hi/lo [b][n][h][v]
    float inv0 = 1.0f / gs0, inv1 = 1.0f / gs1;
    size_t o0 = ((size_t)(b*NN + grow0)*NH + h)*NV + 2*t4;
    size_t o1 = ((size_t)(b*NN + grow0 + 8)*NH + h)*NV + 2*t4;
#pragma unroll
    for (int jv = 0; jv < 8; jv++) {
        split2(o[jv][0]*inv0, o[jv][1]*inv0, &g_Oh[o0 + 8*jv], &g_Ol[o0 + 8*jv]);
        split2(o[jv][2]*inv1, o[jv][3]*inv1, &g_Oh[o1 + 8*jv], &g_Ol[o1 + 8*jv]);
    }
}

// ---------------------------------------------------------------------------
// Kernel 4: output projection, 2-pass (Po-lo dropped). grid (ND/64, NN/128, NB).
// ---------------------------------------------------------------------------
__global__ void __launch_bounds__(256, 2)
out_proj_kernel(float* __restrict__ Y) {
    int b = blockIdx.z, n0 = blockIdx.y * 128, d0 = blockIdx.x * 64;
    float c[8][4] = {};
    gemm128x64<false, false>(g_Oh + (size_t)(b*NN + n0)*(NH*NV),
                             g_Ol + (size_t)(b*NN + n0)*(NH*NV), NH*NV,
                             g_Poh + (size_t)d0*NV, g_Pol + (size_t)d0*NV, NV,
                             (size_t)ND*NV, NH, c);
    int lane = threadIdx.x & 31, w = threadIdx.x >> 5;
    int gid = lane >> 2, t4 = lane & 3;
    int grow0 = n0 + w*16 + gid;
    size_t r0 = (size_t)(b*NN + grow0)*ND + d0;
#pragma unroll
    for (int j = 0; j < 8; j++) {
        int col = 8*j + 2*t4;
        *(float2*)&Y[r0 + col]        = make_float2(c[j][0], c[j][1]);
        *(float2*)&Y[r0 + 8*ND + col] = make_float2(c[j][2], c[j][3]);
    }
}

// ---------------------------------------------------------------------------
extern "C" void kernel_launch(void* const* d_in, const int* in_sizes, int n_in,
                              void* d_out, int out_size) {
    const float* X    = (const float*)d_in[0];
    const float* Mi   = (const float*)d_in[1];
    const float* mask = (const float*)d_in[2];
    const float* Pq   = (const float*)d_in[3];
    const float* Pk   = (const float*)d_in[4];
    const float* Pv   = (const float*)d_in[5];
    const float* Po   = (const float*)d_in[6];
    float* Y = (float*)d_out;

    cudaFuncSetAttribute(q_proj_kernel,   cudaFuncAttributeMaxDynamicSharedMemorySize, SMEM_G);
    cudaFuncSetAttribute(kv_proj_kernel,  cudaFuncAttributeMaxDynamicSharedMemorySize, SMEM_G);
    cudaFuncSetAttribute(attn_kernel,     cudaFuncAttributeMaxDynamicSharedMemorySize, SMEM_ATT);
    cudaFuncSetAttribute(out_proj_kernel, cudaFuncAttributeMaxDynamicSharedMemorySize, SMEM_G);

    split_all_kernel<<<dim3(2048, 6), 256>>>(X, Mi, Pq, Pk, Pv, Po);

    kv_proj_kernel<<<dim3(NM/128, 2, NB), 256, SMEM_G>>>();
    q_proj_kernel<<<dim3(NN/128, NH, NB), 256, SMEM_G>>>();
    attn_kernel<<<dim3(NN/128, NH, NB), 256, SMEM_ATT>>>(mask);
    out_proj_kernel<<<dim3(ND/64, NN/128, NB), 256, SMEM_G>>>(Y);
}

// round 15
// speedup vs baseline: 1.1950x; 1.0613x over previous
#include <cuda_runtime.h>
#include <cuda_fp16.h>
#include <cstdint>

#define NB 2
#define NN 2048
#define NM 2048
#define ND 1024
#define NH 16
#define NK 64
#define NV 64

// ---------------- scratch (__device__ globals; no allocs allowed) ----------
__device__ __half g_Xh[(size_t)NB*NN*ND],   g_Xl[(size_t)NB*NN*ND];
__device__ __half g_Mh[(size_t)NB*NM*ND],   g_Ml[(size_t)NB*NM*ND];
__device__ __half g_Pqh[(size_t)NH*ND*NK],  g_Pql[(size_t)NH*ND*NK];
__device__ __half g_Pkh[(size_t)ND*NK],     g_Pkl[(size_t)ND*NK];
__device__ __half g_Pvh[(size_t)ND*NV],     g_Pvl[(size_t)ND*NV];
__device__ __half g_Poh[(size_t)NH*ND*NV],  g_Pol[(size_t)NH*ND*NV];
__device__ __half g_Qh[(size_t)NB*NH*NN*NK], g_Ql[(size_t)NB*NH*NN*NK];
__device__ __half g_Kh[(size_t)NB*NM*NK],   g_Kl[(size_t)NB*NM*NK];
__device__ __half g_Vh[(size_t)NB*NM*NV];
__device__ __half g_Oh[(size_t)NB*NN*NH*NV], g_Ol[(size_t)NB*NN*NH*NV];

// ---------------- helpers --------------------------------------------------
__device__ __forceinline__ uint32_t smem_u32(const void* p) {
    uint32_t a;
    asm("{ .reg .u64 t; cvta.to.shared.u64 t, %1; cvt.u32.u64 %0, t; }" : "=r"(a) : "l"(p));
    return a;
}
__device__ __forceinline__ void ldsm_x4(uint32_t (&r)[4], uint32_t a) {
    asm volatile("ldmatrix.sync.aligned.m8n8.x4.shared.b16 {%0,%1,%2,%3}, [%4];"
                 : "=r"(r[0]), "=r"(r[1]), "=r"(r[2]), "=r"(r[3]) : "r"(a));
}
__device__ __forceinline__ void ldsm_x4t(uint32_t (&r)[4], uint32_t a) {
    asm volatile("ldmatrix.sync.aligned.m8n8.x4.trans.shared.b16 {%0,%1,%2,%3}, [%4];"
                 : "=r"(r[0]), "=r"(r[1]), "=r"(r[2]), "=r"(r[3]) : "r"(a));
}
__device__ __forceinline__ void mma16816(float (&c)[4], const uint32_t (&a)[4],
                                         uint32_t b0, uint32_t b1) {
    asm volatile("mma.sync.aligned.m16n8k16.row.col.f32.f16.f16.f32 "
                 "{%0,%1,%2,%3}, {%4,%5,%6,%7}, {%8,%9}, {%0,%1,%2,%3};"
                 : "+f"(c[0]), "+f"(c[1]), "+f"(c[2]), "+f"(c[3])
                 : "r"(a[0]), "r"(a[1]), "r"(a[2]), "r"(a[3]), "r"(b0), "r"(b1));
}
__device__ __forceinline__ uint32_t ex2_h2(uint32_t x) {
    uint32_t r;
    asm volatile("ex2.approx.f16x2 %0, %1;" : "=r"(r) : "r"(x));
    return r;
}
__device__ __forceinline__ void split2(float a, float b, __half* hp, __half* lp) {
    __half h0 = __float2half_rn(a), h1 = __float2half_rn(b);
    *(__half2*)hp = __halves2half2(h0, h1);
    *(__half2*)lp = __halves2half2(__float2half_rn(a - __half2float(h0)),
                                   __float2half_rn(b - __half2float(h1)));
}
#define CP_COMMIT() asm volatile("cp.async.commit_group;" ::: "memory")
#define CP_WAIT1()  asm volatile("cp.async.wait_group 1;" ::: "memory")
#define CP_WAIT0()  asm volatile("cp.async.wait_group 0;" ::: "memory")
#define PF_L2(p)    asm volatile("prefetch.global.L2 [%0];" :: "l"(p))

// swizzled 128B-row f16 tile loader (64 halves per row) — sync version
__device__ __forceinline__ void load_f16_tile(char* s, const __half* g,
                                              int gstride, int rows) {
    for (int i = threadIdx.x; i < rows * 8; i += 256) {
        int row = i >> 3, c = i & 7;
        uint4 v = *(const uint4*)(g + (size_t)row * gstride + c * 8);
        int off = row * 128 + c * 16;
        *(uint4*)(s + (off ^ ((off >> 3) & 0x70))) = v;
    }
}
// cp.async version
__device__ __forceinline__ void load_f16_tile_cp(uint32_t sbase, const __half* g,
                                                 int gstride, int rows) {
    for (int i = threadIdx.x; i < rows * 8; i += 256) {
        int row = i >> 3, c = i & 7;
        int off = row * 128 + c * 16;
        asm volatile("cp.async.cg.shared.global [%0], [%1], 16;"
                     :: "r"(sbase + (off ^ ((off >> 3) & 0x70))),
                        "l"(g + (size_t)row * gstride + c * 8) : "memory");
    }
}
// fragment address helpers (swizzle folded)
__device__ __forceinline__ uint32_t a_addr(uint32_t base, int row0, int ks, int lane) {
    int m = lane >> 3;
    int r = row0 + ((m & 1) << 3) + (lane & 7);
    int cb = ((((m >> 1) << 3) + (ks << 4)) << 1);
    return base + r * 128 + (cb ^ ((r & 7) << 4));
}
// x4 pair: lanes 0-15 -> fragment j, lanes 16-31 -> fragment j+1 (B in [n][k])
__device__ __forceinline__ uint32_t b_addr2(uint32_t base, int j, int ks, int lane) {
    int jj = j + (lane >> 4);
    int l = lane & 15;
    int r = (jj << 3) + (l & 7);
    int cb = (((ks << 4) + ((l >> 3) << 3)) << 1);
    return base + r * 128 + (cb ^ ((l & 7) << 4));
}
// x4 trans pair: lanes 0-15 -> jv, lanes 16-31 -> jv+1 (B in [k][n])
__device__ __forceinline__ uint32_t v_addr2(uint32_t base, int ks, int jv, int lane) {
    int jj = jv + (lane >> 4);
    int l = lane & 15;
    int r = (ks << 4) + l;
    int cb = (jj << 4);
    return base + r * 128 + (cb ^ ((l & 7) << 4));
}

// ---------------------------------------------------------------------------
// Kernel 0: fp32 -> fp16 hi/lo split, ALL tensors in one launch (grid.y = tensor)
// ---------------------------------------------------------------------------
__global__ void split_all_kernel(const float* __restrict__ X, const float* __restrict__ Mi,
                                 const float* __restrict__ Pq, const float* __restrict__ Pk,
                                 const float* __restrict__ Pv, const float* __restrict__ Po) {
    const float* s; __half* hp; __half* lp; size_t n;
    switch (blockIdx.y) {
        case 0: s = X;  hp = g_Xh;  lp = g_Xl;  n = (size_t)NB*NN*ND; break;
        case 1: s = Mi; hp = g_Mh;  lp = g_Ml;  n = (size_t)NB*NM*ND; break;
        case 2: s = Pq; hp = g_Pqh; lp = g_Pql; n = (size_t)NH*ND*NK; break;
        case 3: s = Pk; hp = g_Pkh; lp = g_Pkl; n = (size_t)ND*NK;    break;
        case 4: s = Pv; hp = g_Pvh; lp = g_Pvl; n = (size_t)ND*NV;    break;
        default:s = Po; hp = g_Poh; lp = g_Pol; n = (size_t)NH*ND*NV; break;
    }
    int n4 = (int)(n / 4);
    for (int i = blockIdx.x * blockDim.x + threadIdx.x; i < n4;
         i += gridDim.x * blockDim.x) {
        float4 v = ((const float4*)s)[i];
        split2(v.x, v.y, hp + 4*i,     lp + 4*i);
        split2(v.z, v.w, hp + 4*i + 2, lp + 4*i + 2);
    }
}

// ---------------------------------------------------------------------------
// Shared HMMA core, 2-stage cp.async pipeline, batch-loaded K fragments +
// pass-separated MMA scheduling (8 independent accumulator chains per pass).
// ---------------------------------------------------------------------------
#define GST    49152
#define G_SA_H 0
#define G_SA_L 16384
#define G_SB_H 32768
#define G_SB_L 40960
#define SMEM_G 98304

template <bool TB, bool P3>
__device__ __forceinline__ void gemm128x64(const __half* Ah, const __half* Al, int lda,
                                           const __half* Bh, const __half* Bl, int ldb,
                                           size_t bstep, int nchunks, float (&c)[8][4]) {
    extern __shared__ char smem[];
    uint32_t sb = smem_u32(smem);
    int lane = threadIdx.x & 31, w = threadIdx.x >> 5, wrow0 = w * 16;

    {
        uint32_t st = sb;
        load_f16_tile_cp(st + G_SA_H, Ah, lda, 128);
        load_f16_tile_cp(st + G_SA_L, Al, lda, 128);
        load_f16_tile_cp(st + G_SB_H, Bh, ldb, 64);
        if (P3) load_f16_tile_cp(st + G_SB_L, Bl, ldb, 64);
        CP_COMMIT();
    }
    for (int ch = 0; ch < nchunks; ch++) {
        if (ch + 1 < nchunks) {
            uint32_t st = sb + ((ch + 1) & 1) * GST;
            load_f16_tile_cp(st + G_SA_H, Ah + (ch + 1) * 64, lda, 128);
            load_f16_tile_cp(st + G_SA_L, Al + (ch + 1) * 64, lda, 128);
            load_f16_tile_cp(st + G_SB_H, Bh + (ch + 1) * bstep, ldb, 64);
            if (P3) load_f16_tile_cp(st + G_SB_L, Bl + (ch + 1) * bstep, ldb, 64);
            CP_COMMIT();
            CP_WAIT1();
        } else {
            CP_WAIT0();
        }
        __syncthreads();
        uint32_t st = sb + (ch & 1) * GST;
#pragma unroll
        for (int ks = 0; ks < 4; ks++) {
            uint32_t ah[4], al[4];
            ldsm_x4(ah, a_addr(st + G_SA_H, wrow0, ks, lane));
            ldsm_x4(al, a_addr(st + G_SA_L, wrow0, ks, lane));
            uint32_t bh[4][4];
#pragma unroll
            for (int jp = 0; jp < 4; jp++) {
                if (TB) ldsm_x4t(bh[jp], v_addr2(st + G_SB_H, ks, 2*jp, lane));
                else    ldsm_x4 (bh[jp], b_addr2(st + G_SB_H, 2*jp, ks, lane));
            }
#pragma unroll
            for (int jp = 0; jp < 4; jp++) {
                mma16816(c[2*jp],   ah, bh[jp][0], bh[jp][1]);
                mma16816(c[2*jp+1], ah, bh[jp][2], bh[jp][3]);
            }
#pragma unroll
            for (int jp = 0; jp < 4; jp++) {
                mma16816(c[2*jp],   al, bh[jp][0], bh[jp][1]);
                mma16816(c[2*jp+1], al, bh[jp][2], bh[jp][3]);
            }
            if (P3) {
                uint32_t bl[4][4];
#pragma unroll
                for (int jp = 0; jp < 4; jp++) {
                    if (TB) ldsm_x4t(bl[jp], v_addr2(st + G_SB_L, ks, 2*jp, lane));
                    else    ldsm_x4 (bl[jp], b_addr2(st + G_SB_L, 2*jp, ks, lane));
                }
#pragma unroll
                for (int jp = 0; jp < 4; jp++) {
                    mma16816(c[2*jp],   ah, bl[jp][0], bl[jp][1]);
                    mma16816(c[2*jp+1], ah, bl[jp][2], bl[jp][3]);
                }
            }
        }
        __syncthreads();
    }
}

// ---------------------------------------------------------------------------
// Kernel 1: fused Q/K/V projection. grid (16, NH+2, NB):
//   y <  NH : Q projection for head y (3-pass),  tile x of X
//   y == NH : K projection (3-pass),             tile x of M
//   y == NH+1: V projection (2-pass, hi only),   tile x of M
// Folds kv_proj's 64 CTAs into q_proj's wave structure (576 CTAs total).
// ---------------------------------------------------------------------------
__global__ void __launch_bounds__(256, 2)
qkv_proj_kernel() {
    int b = blockIdx.z, y = blockIdx.y, x0 = blockIdx.x * 128;
    int lane = threadIdx.x & 31, w = threadIdx.x >> 5;
    int gid = lane >> 2, t4 = lane & 3;
    float c[8][4] = {};

    if (y < NH) {
        // ---- Q projection, head y
        gemm128x64<true, true>(g_Xh + (size_t)(b*NN + x0)*ND,
                               g_Xl + (size_t)(b*NN + x0)*ND, ND,
                               g_Pqh + (size_t)y*ND*NK, g_Pql + (size_t)y*ND*NK, NK,
                               (size_t)64*NK, ND/64, c);
        int grow0 = x0 + w*16 + gid;
        size_t r0 = ((size_t)(b*NH + y)*NN + grow0)*NK;
#pragma unroll
        for (int j = 0; j < 8; j++) {
            int col = 8*j + 2*t4;
            split2(c[j][0], c[j][1], &g_Qh[r0 + col], &g_Ql[r0 + col]);
            split2(c[j][2], c[j][3], &g_Qh[r0 + 8*NK + col], &g_Ql[r0 + 8*NK + col]);
        }
    } else if (y == NH) {
        // ---- K projection (3-pass)
        gemm128x64<true, true>(g_Mh + (size_t)(b*NM + x0)*ND,
                               g_Ml + (size_t)(b*NM + x0)*ND, ND,
                               g_Pkh, g_Pkl, NK, (size_t)64*NK, ND/64, c);
        int grow0 = x0 + w*16 + gid;
        size_t r0 = (size_t)(b*NM + grow0)*NK;
#pragma unroll
        for (int j = 0; j < 8; j++) {
            int col = 8*j + 2*t4;
            split2(c[j][0], c[j][1], &g_Kh[r0 + col], &g_Kl[r0 + col]);
            split2(c[j][2], c[j][3], &g_Kh[r0 + 8*NK + col], &g_Kl[r0 + 8*NK + col]);
        }
    } else {
        // ---- V projection (2-pass, hi only consumed)
        gemm128x64<true, false>(g_Mh + (size_t)(b*NM + x0)*ND,
                                g_Ml + (size_t)(b*NM + x0)*ND, ND,
                                g_Pvh, g_Pvl, NK, (size_t)64*NK, ND/64, c);
        int grow0 = x0 + w*16 + gid;
        size_t r0 = (size_t)(b*NM + grow0)*NK;
#pragma unroll
        for (int j = 0; j < 8; j++) {
            int col = 8*j + 2*t4;
            *(__half2*)&g_Vh[r0 + col] =
                __halves2half2(__float2half_rn(c[j][0]), __float2half_rn(c[j][1]));
            *(__half2*)&g_Vh[r0 + 8*NK + col] =
                __halves2half2(__float2half_rn(c[j][2]), __float2half_rn(c[j][3]));
        }
    }
}

// ---------------------------------------------------------------------------
// Kernel 3: mma.sync flash attention — round-10 pipeline + pass-separated
// S-MMA scheduling (batch K-fragment loads, 8 independent chains per pass).
// Stage (24KB): KH 0, KL 8K, VH 16K. Q at 48K/64K. 80KB.
// ---------------------------------------------------------------------------
#define AST    24576
#define A_KH   0
#define A_KL   8192
#define A_VH   16384
#define S_QH   49152
#define S_QL   65536
#define SMEM_ATT 81920
#define L2E 1.4426950408889634f

__global__ void __launch_bounds__(256, 2)
attn_kernel(const float* __restrict__ mask) {
    extern __shared__ char smem[];
    const uint32_t sb = smem_u32(smem);
    const int tid = threadIdx.x;
    const int w = tid >> 5, lane = tid & 31;
    const int gid = lane >> 2, t4 = lane & 3;
    const int wrow0 = w * 16;
    const int b = blockIdx.z, h = blockIdx.y, n0 = blockIdx.x * 128;

    const __half* kh_g = g_Kh + (size_t)b*NM*NK;
    const __half* kl_g = g_Kl + (size_t)b*NM*NK;
    const __half* vh_g = g_Vh + (size_t)b*NM*NV;

    const float* pfb = mask + ((size_t)(b*NH + h)*NN + n0 + wrow0 + (lane >> 1))*(size_t)NM
                            + (lane & 1) * 32;

    {
        load_f16_tile_cp(sb + A_KH, kh_g, NK, 64);
        load_f16_tile_cp(sb + A_KL, kl_g, NK, 64);
        load_f16_tile_cp(sb + A_VH, vh_g, NV, 64);
        CP_COMMIT();
        PF_L2(pfb);
    }
    size_t qoff = ((size_t)(b*NH + h)*NN + n0) * NK;
    load_f16_tile((char*)smem + S_QH, g_Qh + qoff, NK, 128);
    load_f16_tile((char*)smem + S_QL, g_Ql + qoff, NK, 128);
    __syncthreads();

    uint32_t qh[4][4];
#pragma unroll
    for (int ks = 0; ks < 4; ks++) ldsm_x4(qh[ks], a_addr(sb + S_QH, wrow0, ks, lane));

    float o[8][4];
#pragma unroll
    for (int j = 0; j < 8; j++) { o[j][0]=0.f; o[j][1]=0.f; o[j][2]=0.f; o[j][3]=0.f; }
    float gmax0 = -1e30f, gmax1 = -1e30f, gs0 = 0.f, gs1 = 0.f;

    const int grow0 = n0 + wrow0 + gid;
    const float* mp0 = mask + (((size_t)(b*NH + h)*NN + grow0))*(size_t)NM + 2*t4;
    const float* mp1 = mp0 + (size_t)8 * NM;

    const int NIT = NM / 64;
    for (int it = 0; it < NIT; it++) {
        const int m0 = it * 64;
        if (it + 1 < NIT) {
            uint32_t st = sb + ((it + 1) & 1) * AST;
            const int m1 = m0 + 64;
            load_f16_tile_cp(st + A_KH, kh_g + (size_t)m1*NK, NK, 64);
            load_f16_tile_cp(st + A_KL, kl_g + (size_t)m1*NK, NK, 64);
            load_f16_tile_cp(st + A_VH, vh_g + (size_t)m1*NV, NV, 64);
            CP_COMMIT();
            PF_L2(pfb + m1);
            CP_WAIT1();
        } else {
            CP_WAIT0();
        }
        __syncthreads();
        const uint32_t st = sb + (it & 1) * AST;

        float c[8][4];
#pragma unroll
        for (int j = 0; j < 8; j++) { c[j][0]=0.f; c[j][1]=0.f; c[j][2]=0.f; c[j][3]=0.f; }
#pragma unroll
        for (int ks = 0; ks < 4; ks++) {
            uint32_t ql[4];
            ldsm_x4(ql, a_addr(sb + S_QL, wrow0, ks, lane));
            uint32_t bh[4][4], bl[4][4];
#pragma unroll
            for (int jp = 0; jp < 4; jp++)
                ldsm_x4(bh[jp], b_addr2(st + A_KH, 2*jp, ks, lane));
#pragma unroll
            for (int jp = 0; jp < 4; jp++)
                ldsm_x4(bl[jp], b_addr2(st + A_KL, 2*jp, ks, lane));
#pragma unroll
            for (int jp = 0; jp < 4; jp++) {
                mma16816(c[2*jp],   qh[ks], bh[jp][0], bh[jp][1]);
                mma16816(c[2*jp+1], qh[ks], bh[jp][2], bh[jp][3]);
            }
#pragma unroll
            for (int jp = 0; jp < 4; jp++) {
                mma16816(c[2*jp],   ql, bh[jp][0], bh[jp][1]);
                mma16816(c[2*jp+1], ql, bh[jp][2], bh[jp][3]);
            }
#pragma unroll
            for (int jp = 0; jp < 4; jp++) {
                mma16816(c[2*jp],   qh[ks], bl[jp][0], bl[jp][1]);
                mma16816(c[2*jp+1], qh[ks], bl[jp][2], bl[jp][3]);
            }
        }

        float mx0 = -1e30f, mx1 = -1e30f;
#pragma unroll
        for (int j = 0; j < 8; j++) {
            float2 a = *(const float2*)(mp0 + m0 + 8*j);
            float2 d = *(const float2*)(mp1 + m0 + 8*j);
            c[j][0] += a.x; c[j][1] += a.y; c[j][2] += d.x; c[j][3] += d.y;
            mx0 = fmaxf(mx0, fmaxf(c[j][0], c[j][1]));
            mx1 = fmaxf(mx1, fmaxf(c[j][2], c[j][3]));
        }
        mx0 = fmaxf(mx0, __shfl_xor_sync(0xffffffffu, mx0, 1));
        mx0 = fmaxf(mx0, __shfl_xor_sync(0xffffffffu, mx0, 2));
        mx1 = fmaxf(mx1, __shfl_xor_sync(0xffffffffu, mx1, 1));
        mx1 = fmaxf(mx1, __shfl_xor_sync(0xffffffffu, mx1, 2));

        float mn0 = fmaxf(gmax0, mx0), mn1 = fmaxf(gmax1, mx1);
        float sc0 = __expf(gmax0 - mn0), sc1 = __expf(gmax1 - mn1);
        gmax0 = mn0; gmax1 = mn1;

        uint32_t pk[8][2];
        float rs0 = 0.f, rs1 = 0.f;
#pragma unroll
        for (int j = 0; j < 8; j++) {
            __half2 t0 = __floats2half2_rn((c[j][0]-mn0)*L2E, (c[j][1]-mn0)*L2E);
            __half2 t1 = __floats2half2_rn((c[j][2]-mn1)*L2E, (c[j][3]-mn1)*L2E);
            pk[j][0] = ex2_h2(*(uint32_t*)&t0);
            pk[j][1] = ex2_h2(*(uint32_t*)&t1);
            float2 f0 = __half22float2(*(__half2*)&pk[j][0]);
            float2 f1 = __half22float2(*(__half2*)&pk[j][1]);
            rs0 += f0.x + f0.y; rs1 += f1.x + f1.y;
        }
        rs0 += __shfl_xor_sync(0xffffffffu, rs0, 1);
        rs0 += __shfl_xor_sync(0xffffffffu, rs0, 2);
        rs1 += __shfl_xor_sync(0xffffffffu, rs1, 1);
        rs1 += __shfl_xor_sync(0xffffffffu, rs1, 2);
        gs0 = gs0 * sc0 + rs0;
        gs1 = gs1 * sc1 + rs1;

#pragma unroll
        for (int j = 0; j < 8; j++) {
            o[j][0] *= sc0; o[j][1] *= sc0; o[j][2] *= sc1; o[j][3] *= sc1;
        }
#pragma unroll
        for (int ks = 0; ks < 4; ks++) {
            uint32_t pa[4] = { pk[2*ks][0], pk[2*ks][1], pk[2*ks+1][0], pk[2*ks+1][1] };
#pragma unroll
            for (int jv = 0; jv < 8; jv += 2) {
                uint32_t vh[4];
                ldsm_x4t(vh, v_addr2(st + A_VH, ks, jv, lane));
                mma16816(o[jv],   pa, vh[0], vh[1]);
                mma16816(o[jv+1], pa, vh[2], vh[3]);
            }
        }
        __syncthreads();
    }

    // epilogue: normalize, split-store O as fp16 hi/lo [b][n][h][v]
    float inv0 = 1.0f / gs0, inv1 = 1.0f / gs1;
    size_t o0 = ((size_t)(b*NN + grow0)*NH + h)*NV + 2*t4;
    size_t o1 = ((size_t)(b*NN + grow0 + 8)*NH + h)*NV + 2*t4;
#pragma unroll
    for (int jv = 0; jv < 8; jv++) {
        split2(o[jv][0]*inv0, o[jv][1]*inv0, &g_Oh[o0 + 8*jv], &g_Ol[o0 + 8*jv]);
        split2(o[jv][2]*inv1, o[jv][3]*inv1, &g_Oh[o1 + 8*jv], &g_Ol[o1 + 8*jv]);
    }
}

// ---------------------------------------------------------------------------
// Kernel 4: output projection, 2-pass (Po-lo dropped). grid (ND/64, NN/128, NB).
// ---------------------------------------------------------------------------
__global__ void __launch_bounds__(256, 2)
out_proj_kernel(float* __restrict__ Y) {
    int b = blockIdx.z, n0 = blockIdx.y * 128, d0 = blockIdx.x * 64;
    float c[8][4] = {};
    gemm128x64<false, false>(g_Oh + (size_t)(b*NN + n0)*(NH*NV),
                             g_Ol + (size_t)(b*NN + n0)*(NH*NV), NH*NV,
                             g_Poh + (size_t)d0*NV, g_Pol + (size_t)d0*NV, NV,
                             (size_t)ND*NV, NH, c);
    int lane = threadIdx.x & 31, w = threadIdx.x >> 5;
    int gid = lane >> 2, t4 = lane & 3;
    int grow0 = n0 + w*16 + gid;
    size_t r0 = (size_t)(b*NN + grow0)*ND + d0;
#pragma unroll
    for (int j = 0; j < 8; j++) {
        int col = 8*j + 2*t4;
        *(float2*)&Y[r0 + col]        = make_float2(c[j][0], c[j][1]);
        *(float2*)&Y[r0 + 8*ND + col] = make_float2(c[j][2], c[j][3]);
    }
}

// ---------------------------------------------------------------------------
extern "C" void kernel_launch(void* const* d_in, const int* in_sizes, int n_in,
                              void* d_out, int out_size) {
    const float* X    = (const float*)d_in[0];
    const float* Mi   = (const float*)d_in[1];
    const float* mask = (const float*)d_in[2];
    const float* Pq   = (const float*)d_in[3];
    const float* Pk   = (const float*)d_in[4];
    const float* Pv   = (const float*)d_in[5];
    const float* Po   = (const float*)d_in[6];
    float* Y = (float*)d_out;

    cudaFuncSetAttribute(qkv_proj_kernel, cudaFuncAttributeMaxDynamicSharedMemorySize, SMEM_G);
    cudaFuncSetAttribute(attn_kernel,     cudaFuncAttributeMaxDynamicSharedMemorySize, SMEM_ATT);
    cudaFuncSetAttribute(out_proj_kernel, cudaFuncAttributeMaxDynamicSharedMemorySize, SMEM_G);

    split_all_kernel<<<dim3(2048, 6), 256>>>(X, Mi, Pq, Pk, Pv, Po);

    qkv_proj_kernel<<<dim3(NN/128, NH + 2, NB), 256, SMEM_G>>>();
    attn_kernel<<<dim3(NN/128, NH, NB), 256, SMEM_ATT>>>(mask);
    out_proj_kernel<<<dim3(ND/64, NN/128, NB), 256, SMEM_G>>>(Y);
}

// round 16
// speedup vs baseline: 1.1965x; 1.0012x over previous
#include <cuda_runtime.h>
#include <cuda_fp16.h>
#include <cstdint>

#define NB 2
#define NN 2048
#define NM 2048
#define ND 1024
#define NH 16
#define NK 64
#define NV 64

// ---------------- scratch (__device__ globals; no allocs allowed) ----------
__device__ __half g_Xh[(size_t)NB*NN*ND],   g_Xl[(size_t)NB*NN*ND];
__device__ __half g_Mh[(size_t)NB*NM*ND],   g_Ml[(size_t)NB*NM*ND];
__device__ __half g_Pqh[(size_t)NH*ND*NK],  g_Pql[(size_t)NH*ND*NK];
__device__ __half g_Pkh[(size_t)ND*NK],     g_Pkl[(size_t)ND*NK];
__device__ __half g_Pvh[(size_t)ND*NV],     g_Pvl[(size_t)ND*NV];
__device__ __half g_Poh[(size_t)NH*ND*NV],  g_Pol[(size_t)NH*ND*NV];
__device__ __half g_Qh[(size_t)NB*NH*NN*NK], g_Ql[(size_t)NB*NH*NN*NK];
__device__ __half g_Kh[(size_t)NB*NM*NK],   g_Kl[(size_t)NB*NM*NK];
__device__ __half g_Vh[(size_t)NB*NM*NV];
__device__ __half g_Oh[(size_t)NB*NN*NH*NV], g_Ol[(size_t)NB*NN*NH*NV];

// ---------------- helpers --------------------------------------------------
__device__ __forceinline__ uint32_t smem_u32(const void* p) {
    uint32_t a;
    asm("{ .reg .u64 t; cvta.to.shared.u64 t, %1; cvt.u32.u64 %0, t; }" : "=r"(a) : "l"(p));
    return a;
}
__device__ __forceinline__ void ldsm_x4(uint32_t (&r)[4], uint32_t a) {
    asm volatile("ldmatrix.sync.aligned.m8n8.x4.shared.b16 {%0,%1,%2,%3}, [%4];"
                 : "=r"(r[0]), "=r"(r[1]), "=r"(r[2]), "=r"(r[3]) : "r"(a));
}
__device__ __forceinline__ void ldsm_x4t(uint32_t (&r)[4], uint32_t a) {
    asm volatile("ldmatrix.sync.aligned.m8n8.x4.trans.shared.b16 {%0,%1,%2,%3}, [%4];"
                 : "=r"(r[0]), "=r"(r[1]), "=r"(r[2]), "=r"(r[3]) : "r"(a));
}
__device__ __forceinline__ void mma16816(float (&c)[4], const uint32_t (&a)[4],
                                         uint32_t b0, uint32_t b1) {
    asm volatile("mma.sync.aligned.m16n8k16.row.col.f32.f16.f16.f32 "
                 "{%0,%1,%2,%3}, {%4,%5,%6,%7}, {%8,%9}, {%0,%1,%2,%3};"
                 : "+f"(c[0]), "+f"(c[1]), "+f"(c[2]), "+f"(c[3])
                 : "r"(a[0]), "r"(a[1]), "r"(a[2]), "r"(a[3]), "r"(b0), "r"(b1));
}
__device__ __forceinline__ uint32_t ex2_h2(uint32_t x) {
    uint32_t r;
    asm volatile("ex2.approx.f16x2 %0, %1;" : "=r"(r) : "r"(x));
    return r;
}
__device__ __forceinline__ void split2(float a, float b, __half* hp, __half* lp) {
    __half h0 = __float2half_rn(a), h1 = __float2half_rn(b);
    *(__half2*)hp = __halves2half2(h0, h1);
    *(__half2*)lp = __halves2half2(__float2half_rn(a - __half2float(h0)),
                                   __float2half_rn(b - __half2float(h1)));
}
#define CP_COMMIT() asm volatile("cp.async.commit_group;" ::: "memory")
#define CP_WAIT1()  asm volatile("cp.async.wait_group 1;" ::: "memory")
#define CP_WAIT0()  asm volatile("cp.async.wait_group 0;" ::: "memory")
#define PF_L2(p)    asm volatile("prefetch.global.L2 [%0];" :: "l"(p))

// swizzled 128B-row f16 tile loader (64 halves per row) — sync version
__device__ __forceinline__ void load_f16_tile(char* s, const __half* g,
                                              int gstride, int rows) {
    for (int i = threadIdx.x; i < rows * 8; i += 256) {
        int row = i >> 3, c = i & 7;
        uint4 v = *(const uint4*)(g + (size_t)row * gstride + c * 8);
        int off = row * 128 + c * 16;
        *(uint4*)(s + (off ^ ((off >> 3) & 0x70))) = v;
    }
}
// cp.async version
__device__ __forceinline__ void load_f16_tile_cp(uint32_t sbase, const __half* g,
                                                 int gstride, int rows) {
    for (int i = threadIdx.x; i < rows * 8; i += 256) {
        int row = i >> 3, c = i & 7;
        int off = row * 128 + c * 16;
        asm volatile("cp.async.cg.shared.global [%0], [%1], 16;"
                     :: "r"(sbase + (off ^ ((off >> 3) & 0x70))),
                        "l"(g + (size_t)row * gstride + c * 8) : "memory");
    }
}
// fragment address helpers (swizzle folded)
__device__ __forceinline__ uint32_t a_addr(uint32_t base, int row0, int ks, int lane) {
    int m = lane >> 3;
    int r = row0 + ((m & 1) << 3) + (lane & 7);
    int cb = ((((m >> 1) << 3) + (ks << 4)) << 1);
    return base + r * 128 + (cb ^ ((r & 7) << 4));
}
// x4 pair: lanes 0-15 -> fragment j, lanes 16-31 -> fragment j+1 (B in [n][k])
__device__ __forceinline__ uint32_t b_addr2(uint32_t base, int j, int ks, int lane) {
    int jj = j + (lane >> 4);
    int l = lane & 15;
    int r = (jj << 3) + (l & 7);
    int cb = (((ks << 4) + ((l >> 3) << 3)) << 1);
    return base + r * 128 + (cb ^ ((l & 7) << 4));
}
// x4 trans pair: lanes 0-15 -> jv, lanes 16-31 -> jv+1 (B in [k][n])
__device__ __forceinline__ uint32_t v_addr2(uint32_t base, int ks, int jv, int lane) {
    int jj = jv + (lane >> 4);
    int l = lane & 15;
    int r = (ks << 4) + l;
    int cb = (jj << 4);
    return base + r * 128 + (cb ^ ((l & 7) << 4));
}

// ---------------------------------------------------------------------------
// Kernel 0: fp32 -> fp16 hi/lo split, ALL tensors in one launch (grid.y = tensor)
// ---------------------------------------------------------------------------
__global__ void split_all_kernel(const float* __restrict__ X, const float* __restrict__ Mi,
                                 const float* __restrict__ Pq, const float* __restrict__ Pk,
                                 const float* __restrict__ Pv, const float* __restrict__ Po) {
    const float* s; __half* hp; __half* lp; size_t n;
    switch (blockIdx.y) {
        case 0: s = X;  hp = g_Xh;  lp = g_Xl;  n = (size_t)NB*NN*ND; break;
        case 1: s = Mi; hp = g_Mh;  lp = g_Ml;  n = (size_t)NB*NM*ND; break;
        case 2: s = Pq; hp = g_Pqh; lp = g_Pql; n = (size_t)NH*ND*NK; break;
        case 3: s = Pk; hp = g_Pkh; lp = g_Pkl; n = (size_t)ND*NK;    break;
        case 4: s = Pv; hp = g_Pvh; lp = g_Pvl; n = (size_t)ND*NV;    break;
        default:s = Po; hp = g_Poh; lp = g_Pol; n = (size_t)NH*ND*NV; break;
    }
    int n4 = (int)(n / 4);
    for (int i = blockIdx.x * blockDim.x + threadIdx.x; i < n4;
         i += gridDim.x * blockDim.x) {
        float4 v = ((const float4*)s)[i];
        split2(v.x, v.y, hp + 4*i,     lp + 4*i);
        split2(v.z, v.w, hp + 4*i + 2, lp + 4*i + 2);
    }
}

// ---------------------------------------------------------------------------
// Shared HMMA core, 2-stage cp.async pipeline, batch-loaded K fragments +
// pass-separated MMA scheduling (8 independent accumulator chains per pass).
// ---------------------------------------------------------------------------
#define GST    49152
#define G_SA_H 0
#define G_SA_L 16384
#define G_SB_H 32768
#define G_SB_L 40960
#define SMEM_G 98304

template <bool TB, bool P3>
__device__ __forceinline__ void gemm128x64(const __half* Ah, const __half* Al, int lda,
                                           const __half* Bh, const __half* Bl, int ldb,
                                           size_t bstep, int nchunks, float (&c)[8][4]) {
    extern __shared__ char smem[];
    uint32_t sb = smem_u32(smem);
    int lane = threadIdx.x & 31, w = threadIdx.x >> 5, wrow0 = w * 16;

    {
        uint32_t st = sb;
        load_f16_tile_cp(st + G_SA_H, Ah, lda, 128);
        load_f16_tile_cp(st + G_SA_L, Al, lda, 128);
        load_f16_tile_cp(st + G_SB_H, Bh, ldb, 64);
        if (P3) load_f16_tile_cp(st + G_SB_L, Bl, ldb, 64);
        CP_COMMIT();
    }
    for (int ch = 0; ch < nchunks; ch++) {
        if (ch + 1 < nchunks) {
            uint32_t st = sb + ((ch + 1) & 1) * GST;
            load_f16_tile_cp(st + G_SA_H, Ah + (ch + 1) * 64, lda, 128);
            load_f16_tile_cp(st + G_SA_L, Al + (ch + 1) * 64, lda, 128);
            load_f16_tile_cp(st + G_SB_H, Bh + (ch + 1) * bstep, ldb, 64);
            if (P3) load_f16_tile_cp(st + G_SB_L, Bl + (ch + 1) * bstep, ldb, 64);
            CP_COMMIT();
            CP_WAIT1();
        } else {
            CP_WAIT0();
        }
        __syncthreads();
        uint32_t st = sb + (ch & 1) * GST;
#pragma unroll
        for (int ks = 0; ks < 4; ks++) {
            uint32_t ah[4], al[4];
            ldsm_x4(ah, a_addr(st + G_SA_H, wrow0, ks, lane));
            ldsm_x4(al, a_addr(st + G_SA_L, wrow0, ks, lane));
            uint32_t bh[4][4];
#pragma unroll
            for (int jp = 0; jp < 4; jp++) {
                if (TB) ldsm_x4t(bh[jp], v_addr2(st + G_SB_H, ks, 2*jp, lane));
                else    ldsm_x4 (bh[jp], b_addr2(st + G_SB_H, 2*jp, ks, lane));
            }
#pragma unroll
            for (int jp = 0; jp < 4; jp++) {
                mma16816(c[2*jp],   ah, bh[jp][0], bh[jp][1]);
                mma16816(c[2*jp+1], ah, bh[jp][2], bh[jp][3]);
            }
#pragma unroll
            for (int jp = 0; jp < 4; jp++) {
                mma16816(c[2*jp],   al, bh[jp][0], bh[jp][1]);
                mma16816(c[2*jp+1], al, bh[jp][2], bh[jp][3]);
            }
            if (P3) {
                uint32_t bl[4][4];
#pragma unroll
                for (int jp = 0; jp < 4; jp++) {
                    if (TB) ldsm_x4t(bl[jp], v_addr2(st + G_SB_L, ks, 2*jp, lane));
                    else    ldsm_x4 (bl[jp], b_addr2(st + G_SB_L, 2*jp, ks, lane));
                }
#pragma unroll
                for (int jp = 0; jp < 4; jp++) {
                    mma16816(c[2*jp],   ah, bl[jp][0], bl[jp][1]);
                    mma16816(c[2*jp+1], ah, bl[jp][2], bl[jp][3]);
                }
            }
        }
        __syncthreads();
    }
}

// ---------------------------------------------------------------------------
// Kernel 1: fused Q/K/V projection. grid (16, NH+2, NB):
//   y <  NH : Q projection for head y (3-pass),  tile x of X
//   y == NH : K projection (3-pass),             tile x of M
//   y == NH+1: V projection (2-pass, hi only),   tile x of M
// ---------------------------------------------------------------------------
__global__ void __launch_bounds__(256, 2)
qkv_proj_kernel() {
    int b = blockIdx.z, y = blockIdx.y, x0 = blockIdx.x * 128;
    int lane = threadIdx.x & 31, w = threadIdx.x >> 5;
    int gid = lane >> 2, t4 = lane & 3;
    float c[8][4] = {};

    if (y < NH) {
        gemm128x64<true, true>(g_Xh + (size_t)(b*NN + x0)*ND,
                               g_Xl + (size_t)(b*NN + x0)*ND, ND,
                               g_Pqh + (size_t)y*ND*NK, g_Pql + (size_t)y*ND*NK, NK,
                               (size_t)64*NK, ND/64, c);
        int grow0 = x0 + w*16 + gid;
        size_t r0 = ((size_t)(b*NH + y)*NN + grow0)*NK;
#pragma unroll
        for (int j = 0; j < 8; j++) {
            int col = 8*j + 2*t4;
            split2(c[j][0], c[j][1], &g_Qh[r0 + col], &g_Ql[r0 + col]);
            split2(c[j][2], c[j][3], &g_Qh[r0 + 8*NK + col], &g_Ql[r0 + 8*NK + col]);
        }
    } else if (y == NH) {
        gemm128x64<true, true>(g_Mh + (size_t)(b*NM + x0)*ND,
                               g_Ml + (size_t)(b*NM + x0)*ND, ND,
                               g_Pkh, g_Pkl, NK, (size_t)64*NK, ND/64, c);
        int grow0 = x0 + w*16 + gid;
        size_t r0 = (size_t)(b*NM + grow0)*NK;
#pragma unroll
        for (int j = 0; j < 8; j++) {
            int col = 8*j + 2*t4;
            split2(c[j][0], c[j][1], &g_Kh[r0 + col], &g_Kl[r0 + col]);
            split2(c[j][2], c[j][3], &g_Kh[r0 + 8*NK + col], &g_Kl[r0 + 8*NK + col]);
        }
    } else {
        gemm128x64<true, false>(g_Mh + (size_t)(b*NM + x0)*ND,
                                g_Ml + (size_t)(b*NM + x0)*ND, ND,
                                g_Pvh, g_Pvl, NK, (size_t)64*NK, ND/64, c);
        int grow0 = x0 + w*16 + gid;
        size_t r0 = (size_t)(b*NM + grow0)*NK;
#pragma unroll
        for (int j = 0; j < 8; j++) {
            int col = 8*j + 2*t4;
            *(__half2*)&g_Vh[r0 + col] =
                __halves2half2(__float2half_rn(c[j][0]), __float2half_rn(c[j][1]));
            *(__half2*)&g_Vh[r0 + 8*NK + col] =
                __halves2half2(__float2half_rn(c[j][2]), __float2half_rn(c[j][3]));
        }
    }
}

// ---------------------------------------------------------------------------
// Kernel 3: mma.sync flash attention — round-10 pipeline + pass-separated
// S-MMA + V-fragment hoist: ks=0,1 V ldsm issued right after S-MMA (where
// the 32 bh/bl regs die) so their latency drains under the softmax stretch.
// Stage (24KB): KH 0, KL 8K, VH 16K. Q at 48K/64K. 80KB.
// ---------------------------------------------------------------------------
#define AST    24576
#define A_KH   0
#define A_KL   8192
#define A_VH   16384
#define S_QH   49152
#define S_QL   65536
#define SMEM_ATT 81920
#define L2E 1.4426950408889634f

__global__ void __launch_bounds__(256, 2)
attn_kernel(const float* __restrict__ mask) {
    extern __shared__ char smem[];
    const uint32_t sb = smem_u32(smem);
    const int tid = threadIdx.x;
    const int w = tid >> 5, lane = tid & 31;
    const int gid = lane >> 2, t4 = lane & 3;
    const int wrow0 = w * 16;
    const int b = blockIdx.z, h = blockIdx.y, n0 = blockIdx.x * 128;

    const __half* kh_g = g_Kh + (size_t)b*NM*NK;
    const __half* kl_g = g_Kl + (size_t)b*NM*NK;
    const __half* vh_g = g_Vh + (size_t)b*NM*NV;

    const float* pfb = mask + ((size_t)(b*NH + h)*NN + n0 + wrow0 + (lane >> 1))*(size_t)NM
                            + (lane & 1) * 32;

    {
        load_f16_tile_cp(sb + A_KH, kh_g, NK, 64);
        load_f16_tile_cp(sb + A_KL, kl_g, NK, 64);
        load_f16_tile_cp(sb + A_VH, vh_g, NV, 64);
        CP_COMMIT();
        PF_L2(pfb);
    }
    size_t qoff = ((size_t)(b*NH + h)*NN + n0) * NK;
    load_f16_tile((char*)smem + S_QH, g_Qh + qoff, NK, 128);
    load_f16_tile((char*)smem + S_QL, g_Ql + qoff, NK, 128);
    __syncthreads();

    uint32_t qh[4][4];
#pragma unroll
    for (int ks = 0; ks < 4; ks++) ldsm_x4(qh[ks], a_addr(sb + S_QH, wrow0, ks, lane));

    float o[8][4];
#pragma unroll
    for (int j = 0; j < 8; j++) { o[j][0]=0.f; o[j][1]=0.f; o[j][2]=0.f; o[j][3]=0.f; }
    float gmax0 = -1e30f, gmax1 = -1e30f, gs0 = 0.f, gs1 = 0.f;

    const int grow0 = n0 + wrow0 + gid;
    const float* mp0 = mask + (((size_t)(b*NH + h)*NN + grow0))*(size_t)NM + 2*t4;
    const float* mp1 = mp0 + (size_t)8 * NM;

    const int NIT = NM / 64;
    for (int it = 0; it < NIT; it++) {
        const int m0 = it * 64;
        if (it + 1 < NIT) {
            uint32_t st = sb + ((it + 1) & 1) * AST;
            const int m1 = m0 + 64;
            load_f16_tile_cp(st + A_KH, kh_g + (size_t)m1*NK, NK, 64);
            load_f16_tile_cp(st + A_KL, kl_g + (size_t)m1*NK, NK, 64);
            load_f16_tile_cp(st + A_VH, vh_g + (size_t)m1*NV, NV, 64);
            CP_COMMIT();
            PF_L2(pfb + m1);
            CP_WAIT1();
        } else {
            CP_WAIT0();
        }
        __syncthreads();
        const uint32_t st = sb + (it & 1) * AST;

        float c[8][4];
#pragma unroll
        for (int j = 0; j < 8; j++) { c[j][0]=0.f; c[j][1]=0.f; c[j][2]=0.f; c[j][3]=0.f; }
#pragma unroll
        for (int ks = 0; ks < 4; ks++) {
            uint32_t ql[4];
            ldsm_x4(ql, a_addr(sb + S_QL, wrow0, ks, lane));
            uint32_t bh[4][4], bl[4][4];
#pragma unroll
            for (int jp = 0; jp < 4; jp++)
                ldsm_x4(bh[jp], b_addr2(st + A_KH, 2*jp, ks, lane));
#pragma unroll
            for (int jp = 0; jp < 4; jp++)
                ldsm_x4(bl[jp], b_addr2(st + A_KL, 2*jp, ks, lane));
#pragma unroll
            for (int jp = 0; jp < 4; jp++) {
                mma16816(c[2*jp],   qh[ks], bh[jp][0], bh[jp][1]);
                mma16816(c[2*jp+1], qh[ks], bh[jp][2], bh[jp][3]);
            }
#pragma unroll
            for (int jp = 0; jp < 4; jp++) {
                mma16816(c[2*jp],   ql, bh[jp][0], bh[jp][1]);
                mma16816(c[2*jp+1], ql, bh[jp][2], bh[jp][3]);
            }
#pragma unroll
            for (int jp = 0; jp < 4; jp++) {
                mma16816(c[2*jp],   qh[ks], bl[jp][0], bl[jp][1]);
                mma16816(c[2*jp+1], qh[ks], bl[jp][2], bl[jp][3]);
            }
        }

        // ---- hoisted V loads for ks=0,1: issue now, drain under softmax ----
        uint32_t vpre[4][4];
#pragma unroll
        for (int ks = 0; ks < 2; ks++)
#pragma unroll
            for (int jv2 = 0; jv2 < 2; jv2++)
                ldsm_x4t(vpre[ks*2 + jv2], v_addr2(st + A_VH, ks, jv2*4, lane));
        // NOTE: vpre[ks*2+jv2] covers (ks, jv=4*jv2 .. 4*jv2+1)? No — v_addr2
        // pairs (jv, jv+1); we load jv=0 and jv=4 pairs per ks here, the
        // remaining jv=2,6 pairs load in the PV loop below.

        float mx0 = -1e30f, mx1 = -1e30f;
#pragma unroll
        for (int j = 0; j < 8; j++) {
            float2 a = *(const float2*)(mp0 + m0 + 8*j);
            float2 d = *(const float2*)(mp1 + m0 + 8*j);
            c[j][0] += a.x; c[j][1] += a.y; c[j][2] += d.x; c[j][3] += d.y;
            mx0 = fmaxf(mx0, fmaxf(c[j][0], c[j][1]));
            mx1 = fmaxf(mx1, fmaxf(c[j][2], c[j][3]));
        }
        mx0 = fmaxf(mx0, __shfl_xor_sync(0xffffffffu, mx0, 1));
        mx0 = fmaxf(mx0, __shfl_xor_sync(0xffffffffu, mx0, 2));
        mx1 = fmaxf(mx1, __shfl_xor_sync(0xffffffffu, mx1, 1));
        mx1 = fmaxf(mx1, __shfl_xor_sync(0xffffffffu, mx1, 2));

        float mn0 = fmaxf(gmax0, mx0), mn1 = fmaxf(gmax1, mx1);
        float sc0 = __expf(gmax0 - mn0), sc1 = __expf(gmax1 - mn1);
        gmax0 = mn0; gmax1 = mn1;

        uint32_t pk[8][2];
        float rs0 = 0.f, rs1 = 0.f;
#pragma unroll
        for (int j = 0; j < 8; j++) {
            __half2 t0 = __floats2half2_rn((c[j][0]-mn0)*L2E, (c[j][1]-mn0)*L2E);
            __half2 t1 = __floats2half2_rn((c[j][2]-mn1)*L2E, (c[j][3]-mn1)*L2E);
            pk[j][0] = ex2_h2(*(uint32_t*)&t0);
            pk[j][1] = ex2_h2(*(uint32_t*)&t1);
            float2 f0 = __half22float2(*(__half2*)&pk[j][0]);
            float2 f1 = __half22float2(*(__half2*)&pk[j][1]);
            rs0 += f0.x + f0.y; rs1 += f1.x + f1.y;
        }
        rs0 += __shfl_xor_sync(0xffffffffu, rs0, 1);
        rs0 += __shfl_xor_sync(0xffffffffu, rs0, 2);
        rs1 += __shfl_xor_sync(0xffffffffu, rs1, 1);
        rs1 += __shfl_xor_sync(0xffffffffu, rs1, 2);
        gs0 = gs0 * sc0 + rs0;
        gs1 = gs1 * sc1 + rs1;

#pragma unroll
        for (int j = 0; j < 8; j++) {
            o[j][0] *= sc0; o[j][1] *= sc0; o[j][2] *= sc1; o[j][3] *= sc1;
        }
        // ---- PV: ks=0,1 use hoisted fragments (jv pairs 0 and 4), the rest
        //      load in place.
#pragma unroll
        for (int ks = 0; ks < 4; ks++) {
            uint32_t pa[4] = { pk[2*ks][0], pk[2*ks][1], pk[2*ks+1][0], pk[2*ks+1][1] };
#pragma unroll
            for (int jv2 = 0; jv2 < 2; jv2++) {
                uint32_t vh[4];
                if (ks < 2) {
#pragma unroll
                    for (int q = 0; q < 4; q++) vh[q] = vpre[ks*2 + jv2][q];
                } else {
                    ldsm_x4t(vh, v_addr2(st + A_VH, ks, jv2*4, lane));
                }
                mma16816(o[jv2*4],     pa, vh[0], vh[1]);
                mma16816(o[jv2*4 + 1], pa, vh[2], vh[3]);
                uint32_t vh2[4];
                ldsm_x4t(vh2, v_addr2(st + A_VH, ks, jv2*4 + 2, lane));
                mma16816(o[jv2*4 + 2], pa, vh2[0], vh2[1]);
                mma16816(o[jv2*4 + 3], pa, vh2[2], vh2[3]);
            }
        }
        __syncthreads();
    }

    // epilogue: normalize, split-store O as fp16 hi/lo [b][n][h][v]
    float inv0 = 1.0f / gs0, inv1 = 1.0f / gs1;
    size_t o0 = ((size_t)(b*NN + grow0)*NH + h)*NV + 2*t4;
    size_t o1 = ((size_t)(b*NN + grow0 + 8)*NH + h)*NV + 2*t4;
#pragma unroll
    for (int jv = 0; jv < 8; jv++) {
        split2(o[jv][0]*inv0, o[jv][1]*inv0, &g_Oh[o0 + 8*jv], &g_Ol[o0 + 8*jv]);
        split2(o[jv][2]*inv1, o[jv][3]*inv1, &g_Oh[o1 + 8*jv], &g_Ol[o1 + 8*jv]);
    }
}

// ---------------------------------------------------------------------------
// Kernel 4: output projection, 2-pass (Po-lo dropped). grid (ND/64, NN/128, NB).
// ---------------------------------------------------------------------------
__global__ void __launch_bounds__(256, 2)
out_proj_kernel(float* __restrict__ Y) {
    int b = blockIdx.z, n0 = blockIdx.y * 128, d0 = blockIdx.x * 64;
    float c[8][4] = {};
    gemm128x64<false, false>(g_Oh + (size_t)(b*NN + n0)*(NH*NV),
                             g_Ol + (size_t)(b*NN + n0)*(NH*NV), NH*NV,
                             g_Poh + (size_t)d0*NV, g_Pol + (size_t)d0*NV, NV,
                             (size_t)ND*NV, NH, c);
    int lane = threadIdx.x & 31, w = threadIdx.x >> 5;
    int gid = lane >> 2, t4 = lane & 3;
    int grow0 = n0 + w*16 + gid;
    size_t r0 = (size_t)(b*NN + grow0)*ND + d0;
#pragma unroll
    for (int j = 0; j < 8; j++) {
        int col = 8*j + 2*t4;
        *(float2*)&Y[r0 + col]        = make_float2(c[j][0], c[j][1]);
        *(float2*)&Y[r0 + 8*ND + col] = make_float2(c[j][2], c[j][3]);
    }
}

// ---------------------------------------------------------------------------
extern "C" void kernel_launch(void* const* d_in, const int* in_sizes, int n_in,
                              void* d_out, int out_size) {
    const float* X    = (const float*)d_in[0];
    const float* Mi   = (const float*)d_in[1];
    const float* mask = (const float*)d_in[2];
    const float* Pq   = (const float*)d_in[3];
    const float* Pk   = (const float*)d_in[4];
    const float* Pv   = (const float*)d_in[5];
    const float* Po   = (const float*)d_in[6];
    float* Y = (float*)d_out;

    cudaFuncSetAttribute(qkv_proj_kernel, cudaFuncAttributeMaxDynamicSharedMemorySize, SMEM_G);
    cudaFuncSetAttribute(attn_kernel,     cudaFuncAttributeMaxDynamicSharedMemorySize, SMEM_ATT);
    cudaFuncSetAttribute(out_proj_kernel, cudaFuncAttributeMaxDynamicSharedMemorySize, SMEM_G);

    split_all_kernel<<<dim3(2048, 6), 256>>>(X, Mi, Pq, Pk, Pv, Po);

    qkv_proj_kernel<<<dim3(NN/128, NH + 2, NB), 256, SMEM_G>>>();
    attn_kernel<<<dim3(NN/128, NH, NB), 256, SMEM_ATT>>>(mask);
    out_proj_kernel<<<dim3(ND/64, NN/128, NB), 256, SMEM_G>>>(Y);
}

// round 17
// speedup vs baseline: 1.2570x; 1.0506x over previous
#include <cuda_runtime.h>
#include <cuda_fp16.h>
#include <cstdint>

#define NB 2
#define NN 2048
#define NM 2048
#define ND 1024
#define NH 16
#define NK 64
#define NV 64

// ---------------- scratch (__device__ globals; no allocs allowed) ----------
__device__ __half g_Xh[(size_t)NB*NN*ND],   g_Xl[(size_t)NB*NN*ND];
__device__ __half g_Mh[(size_t)NB*NM*ND],   g_Ml[(size_t)NB*NM*ND];
__device__ __half g_Pqh[(size_t)NH*ND*NK],  g_Pql[(size_t)NH*ND*NK];
__device__ __half g_Pkh[(size_t)ND*NK],     g_Pkl[(size_t)ND*NK];
__device__ __half g_Pvh[(size_t)ND*NV],     g_Pvl[(size_t)ND*NV];
__device__ __half g_Poh[(size_t)NH*ND*NV],  g_Pol[(size_t)NH*ND*NV];
__device__ __half g_Qh[(size_t)NB*NH*NN*NK], g_Ql[(size_t)NB*NH*NN*NK];
__device__ __half g_Kh[(size_t)NB*NM*NK],   g_Kl[(size_t)NB*NM*NK];
__device__ __half g_Vh[(size_t)NB*NM*NV];
__device__ __half g_Oh[(size_t)NB*NN*NH*NV];

// ---------------- helpers --------------------------------------------------
__device__ __forceinline__ uint32_t smem_u32(const void* p) {
    uint32_t a;
    asm("{ .reg .u64 t; cvta.to.shared.u64 t, %1; cvt.u32.u64 %0, t; }" : "=r"(a) : "l"(p));
    return a;
}
__device__ __forceinline__ void ldsm_x4(uint32_t (&r)[4], uint32_t a) {
    asm volatile("ldmatrix.sync.aligned.m8n8.x4.shared.b16 {%0,%1,%2,%3}, [%4];"
                 : "=r"(r[0]), "=r"(r[1]), "=r"(r[2]), "=r"(r[3]) : "r"(a));
}
__device__ __forceinline__ void ldsm_x4t(uint32_t (&r)[4], uint32_t a) {
    asm volatile("ldmatrix.sync.aligned.m8n8.x4.trans.shared.b16 {%0,%1,%2,%3}, [%4];"
                 : "=r"(r[0]), "=r"(r[1]), "=r"(r[2]), "=r"(r[3]) : "r"(a));
}
__device__ __forceinline__ void mma16816(float (&c)[4], const uint32_t (&a)[4],
                                         uint32_t b0, uint32_t b1) {
    asm volatile("mma.sync.aligned.m16n8k16.row.col.f32.f16.f16.f32 "
                 "{%0,%1,%2,%3}, {%4,%5,%6,%7}, {%8,%9}, {%0,%1,%2,%3};"
                 : "+f"(c[0]), "+f"(c[1]), "+f"(c[2]), "+f"(c[3])
                 : "r"(a[0]), "r"(a[1]), "r"(a[2]), "r"(a[3]), "r"(b0), "r"(b1));
}
__device__ __forceinline__ uint32_t ex2_h2(uint32_t x) {
    uint32_t r;
    asm volatile("ex2.approx.f16x2 %0, %1;" : "=r"(r) : "r"(x));
    return r;
}
__device__ __forceinline__ void split2(float a, float b, __half* hp, __half* lp) {
    __half h0 = __float2half_rn(a), h1 = __float2half_rn(b);
    *(__half2*)hp = __halves2half2(h0, h1);
    *(__half2*)lp = __halves2half2(__float2half_rn(a - __half2float(h0)),
                                   __float2half_rn(b - __half2float(h1)));
}
#define CP_COMMIT() asm volatile("cp.async.commit_group;" ::: "memory")
#define CP_WAIT1()  asm volatile("cp.async.wait_group 1;" ::: "memory")
#define CP_WAIT0()  asm volatile("cp.async.wait_group 0;" ::: "memory")
#define PF_L2(p)    asm volatile("prefetch.global.L2 [%0];" :: "l"(p))

// swizzled 128B-row f16 tile loader (64 halves per row) — sync version
__device__ __forceinline__ void load_f16_tile(char* s, const __half* g,
                                              int gstride, int rows) {
    for (int i = threadIdx.x; i < rows * 8; i += 256) {
        int row = i >> 3, c = i & 7;
        uint4 v = *(const uint4*)(g + (size_t)row * gstride + c * 8);
        int off = row * 128 + c * 16;
        *(uint4*)(s + (off ^ ((off >> 3) & 0x70))) = v;
    }
}
// cp.async version
__device__ __forceinline__ void load_f16_tile_cp(uint32_t sbase, const __half* g,
                                                 int gstride, int rows) {
    for (int i = threadIdx.x; i < rows * 8; i += 256) {
        int row = i >> 3, c = i & 7;
        int off = row * 128 + c * 16;
        asm volatile("cp.async.cg.shared.global [%0], [%1], 16;"
                     :: "r"(sbase + (off ^ ((off >> 3) & 0x70))),
                        "l"(g + (size_t)row * gstride + c * 8) : "memory");
    }
}
// fragment address helpers (swizzle folded)
__device__ __forceinline__ uint32_t a_addr(uint32_t base, int row0, int ks, int lane) {
    int m = lane >> 3;
    int r = row0 + ((m & 1) << 3) + (lane & 7);
    int cb = ((((m >> 1) << 3) + (ks << 4)) << 1);
    return base + r * 128 + (cb ^ ((r & 7) << 4));
}
// x4 pair: lanes 0-15 -> fragment j, lanes 16-31 -> fragment j+1 (B in [n][k])
__device__ __forceinline__ uint32_t b_addr2(uint32_t base, int j, int ks, int lane) {
    int jj = j + (lane >> 4);
    int l = lane & 15;
    int r = (jj << 3) + (l & 7);
    int cb = (((ks << 4) + ((l >> 3) << 3)) << 1);
    return base + r * 128 + (cb ^ ((l & 7) << 4));
}
// x4 trans pair: lanes 0-15 -> jv, lanes 16-31 -> jv+1 (B in [k][n])
__device__ __forceinline__ uint32_t v_addr2(uint32_t base, int ks, int jv, int lane) {
    int jj = jv + (lane >> 4);
    int l = lane & 15;
    int r = (ks << 4) + l;
    int cb = (jj << 4);
    return base + r * 128 + (cb ^ ((l & 7) << 4));
}

// ---------------------------------------------------------------------------
// Kernel 0: fp32 -> fp16 hi/lo split, ALL tensors in one launch (grid.y = tensor)
// ---------------------------------------------------------------------------
__global__ void split_all_kernel(const float* __restrict__ X, const float* __restrict__ Mi,
                                 const float* __restrict__ Pq, const float* __restrict__ Pk,
                                 const float* __restrict__ Pv, const float* __restrict__ Po) {
    const float* s; __half* hp; __half* lp; size_t n;
    switch (blockIdx.y) {
        case 0: s = X;  hp = g_Xh;  lp = g_Xl;  n = (size_t)NB*NN*ND; break;
        case 1: s = Mi; hp = g_Mh;  lp = g_Ml;  n = (size_t)NB*NM*ND; break;
        case 2: s = Pq; hp = g_Pqh; lp = g_Pql; n = (size_t)NH*ND*NK; break;
        case 3: s = Pk; hp = g_Pkh; lp = g_Pkl; n = (size_t)ND*NK;    break;
        case 4: s = Pv; hp = g_Pvh; lp = g_Pvl; n = (size_t)ND*NV;    break;
        default:s = Po; hp = g_Poh; lp = g_Pol; n = (size_t)NH*ND*NV; break;
    }
    int n4 = (int)(n / 4);
    for (int i = blockIdx.x * blockDim.x + threadIdx.x; i < n4;
         i += gridDim.x * blockDim.x) {
        float4 v = ((const float4*)s)[i];
        split2(v.x, v.y, hp + 4*i,     lp + 4*i);
        split2(v.z, v.w, hp + 4*i + 2, lp + 4*i + 2);
    }
}

// ---------------------------------------------------------------------------
// Shared HMMA core, 2-stage cp.async pipeline, batch-loaded B fragments +
// pass-separated MMA scheduling.
//   TB: B stored [k][n] (trans ldsm)  |  AL: include A-lo pass (al*bh)
//   BL: include B-lo pass (ah*bl)
// ---------------------------------------------------------------------------
#define GST    49152
#define G_SA_H 0
#define G_SA_L 16384
#define G_SB_H 32768
#define G_SB_L 40960
#define SMEM_G 98304

template <bool TB, bool AL, bool BL>
__device__ __forceinline__ void gemm128x64(const __half* Ah, const __half* Al, int lda,
                                           const __half* Bh, const __half* Bl, int ldb,
                                           size_t bstep, int nchunks, float (&c)[8][4]) {
    extern __shared__ char smem[];
    uint32_t sb = smem_u32(smem);
    int lane = threadIdx.x & 31, w = threadIdx.x >> 5, wrow0 = w * 16;

    {
        uint32_t st = sb;
        load_f16_tile_cp(st + G_SA_H, Ah, lda, 128);
        if (AL) load_f16_tile_cp(st + G_SA_L, Al, lda, 128);
        load_f16_tile_cp(st + G_SB_H, Bh, ldb, 64);
        if (BL) load_f16_tile_cp(st + G_SB_L, Bl, ldb, 64);
        CP_COMMIT();
    }
    for (int ch = 0; ch < nchunks; ch++) {
        if (ch + 1 < nchunks) {
            uint32_t st = sb + ((ch + 1) & 1) * GST;
            load_f16_tile_cp(st + G_SA_H, Ah + (ch + 1) * 64, lda, 128);
            if (AL) load_f16_tile_cp(st + G_SA_L, Al + (ch + 1) * 64, lda, 128);
            load_f16_tile_cp(st + G_SB_H, Bh + (ch + 1) * bstep, ldb, 64);
            if (BL) load_f16_tile_cp(st + G_SB_L, Bl + (ch + 1) * bstep, ldb, 64);
            CP_COMMIT();
            CP_WAIT1();
        } else {
            CP_WAIT0();
        }
        __syncthreads();
        uint32_t st = sb + (ch & 1) * GST;
#pragma unroll
        for (int ks = 0; ks < 4; ks++) {
            uint32_t ah[4], al[4];
            ldsm_x4(ah, a_addr(st + G_SA_H, wrow0, ks, lane));
            if (AL) ldsm_x4(al, a_addr(st + G_SA_L, wrow0, ks, lane));
            uint32_t bh[4][4];
#pragma unroll
            for (int jp = 0; jp < 4; jp++) {
                if (TB) ldsm_x4t(bh[jp], v_addr2(st + G_SB_H, ks, 2*jp, lane));
                else    ldsm_x4 (bh[jp], b_addr2(st + G_SB_H, 2*jp, ks, lane));
            }
#pragma unroll
            for (int jp = 0; jp < 4; jp++) {
                mma16816(c[2*jp],   ah, bh[jp][0], bh[jp][1]);
                mma16816(c[2*jp+1], ah, bh[jp][2], bh[jp][3]);
            }
            if (AL) {
#pragma unroll
                for (int jp = 0; jp < 4; jp++) {
                    mma16816(c[2*jp],   al, bh[jp][0], bh[jp][1]);
                    mma16816(c[2*jp+1], al, bh[jp][2], bh[jp][3]);
                }
            }
            if (BL) {
                uint32_t bl[4][4];
#pragma unroll
                for (int jp = 0; jp < 4; jp++) {
                    if (TB) ldsm_x4t(bl[jp], v_addr2(st + G_SB_L, ks, 2*jp, lane));
                    else    ldsm_x4 (bl[jp], b_addr2(st + G_SB_L, 2*jp, ks, lane));
                }
#pragma unroll
                for (int jp = 0; jp < 4; jp++) {
                    mma16816(c[2*jp],   ah, bl[jp][0], bl[jp][1]);
                    mma16816(c[2*jp+1], ah, bl[jp][2], bl[jp][3]);
                }
            }
        }
        __syncthreads();
    }
}

// ---------------------------------------------------------------------------
// Kernel 1: fused Q/K/V projection. grid (16, NH+2, NB):
//   y <  NH : Q projection for head y (3-pass),  tile x of X
//   y == NH : K projection (3-pass),             tile x of M
//   y == NH+1: V projection (2-pass, hi only),   tile x of M
// ---------------------------------------------------------------------------
__global__ void __launch_bounds__(256, 2)
qkv_proj_kernel() {
    int b = blockIdx.z, y = blockIdx.y, x0 = blockIdx.x * 128;
    int lane = threadIdx.x & 31, w = threadIdx.x >> 5;
    int gid = lane >> 2, t4 = lane & 3;
    float c[8][4] = {};

    if (y < NH) {
        gemm128x64<true, true, true>(g_Xh + (size_t)(b*NN + x0)*ND,
                                     g_Xl + (size_t)(b*NN + x0)*ND, ND,
                                     g_Pqh + (size_t)y*ND*NK, g_Pql + (size_t)y*ND*NK, NK,
                                     (size_t)64*NK, ND/64, c);
        int grow0 = x0 + w*16 + gid;
        size_t r0 = ((size_t)(b*NH + y)*NN + grow0)*NK;
#pragma unroll
        for (int j = 0; j < 8; j++) {
            int col = 8*j + 2*t4;
            split2(c[j][0], c[j][1], &g_Qh[r0 + col], &g_Ql[r0 + col]);
            split2(c[j][2], c[j][3], &g_Qh[r0 + 8*NK + col], &g_Ql[r0 + 8*NK + col]);
        }
    } else if (y == NH) {
        gemm128x64<true, true, true>(g_Mh + (size_t)(b*NM + x0)*ND,
                                     g_Ml + (size_t)(b*NM + x0)*ND, ND,
                                     g_Pkh, g_Pkl, NK, (size_t)64*NK, ND/64, c);
        int grow0 = x0 + w*16 + gid;
        size_t r0 = (size_t)(b*NM + grow0)*NK;
#pragma unroll
        for (int j = 0; j < 8; j++) {
            int col = 8*j + 2*t4;
            split2(c[j][0], c[j][1], &g_Kh[r0 + col], &g_Kl[r0 + col]);
            split2(c[j][2], c[j][3], &g_Kh[r0 + 8*NK + col], &g_Kl[r0 + 8*NK + col]);
        }
    } else {
        gemm128x64<true, true, false>(g_Mh + (size_t)(b*NM + x0)*ND,
                                      g_Ml + (size_t)(b*NM + x0)*ND, ND,
                                      g_Pvh, g_Pvl, NK, (size_t)64*NK, ND/64, c);
        int grow0 = x0 + w*16 + gid;
        size_t r0 = (size_t)(b*NM + grow0)*NK;
#pragma unroll
        for (int j = 0; j < 8; j++) {
            int col = 8*j + 2*t4;
            *(__half2*)&g_Vh[r0 + col] =
                __halves2half2(__float2half_rn(c[j][0]), __float2half_rn(c[j][1]));
            *(__half2*)&g_Vh[r0 + 8*NK + col] =
                __halves2half2(__float2half_rn(c[j][2]), __float2half_rn(c[j][3]));
        }
    }
}

// ---------------------------------------------------------------------------
// Kernel 3: mma.sync flash attention — round-10 pipeline + pass-separated
// S-MMA scheduling. Epilogue stores O-hi only (out_proj is 1-pass now).
// Stage (24KB): KH 0, KL 8K, VH 16K. Q at 48K/64K. 80KB.
// ---------------------------------------------------------------------------
#define AST    24576
#define A_KH   0
#define A_KL   8192
#define A_VH   16384
#define S_QH   49152
#define S_QL   65536
#define SMEM_ATT 81920
#define L2E 1.4426950408889634f

__global__ void __launch_bounds__(256, 2)
attn_kernel(const float* __restrict__ mask) {
    extern __shared__ char smem[];
    const uint32_t sb = smem_u32(smem);
    const int tid = threadIdx.x;
    const int w = tid >> 5, lane = tid & 31;
    const int gid = lane >> 2, t4 = lane & 3;
    const int wrow0 = w * 16;
    const int b = blockIdx.z, h = blockIdx.y, n0 = blockIdx.x * 128;

    const __half* kh_g = g_Kh + (size_t)b*NM*NK;
    const __half* kl_g = g_Kl + (size_t)b*NM*NK;
    const __half* vh_g = g_Vh + (size_t)b*NM*NV;

    const float* pfb = mask + ((size_t)(b*NH + h)*NN + n0 + wrow0 + (lane >> 1))*(size_t)NM
                            + (lane & 1) * 32;

    {
        load_f16_tile_cp(sb + A_KH, kh_g, NK, 64);
        load_f16_tile_cp(sb + A_KL, kl_g, NK, 64);
        load_f16_tile_cp(sb + A_VH, vh_g, NV, 64);
        CP_COMMIT();
        PF_L2(pfb);
    }
    size_t qoff = ((size_t)(b*NH + h)*NN + n0) * NK;
    load_f16_tile((char*)smem + S_QH, g_Qh + qoff, NK, 128);
    load_f16_tile((char*)smem + S_QL, g_Ql + qoff, NK, 128);
    __syncthreads();

    uint32_t qh[4][4];
#pragma unroll
    for (int ks = 0; ks < 4; ks++) ldsm_x4(qh[ks], a_addr(sb + S_QH, wrow0, ks, lane));

    float o[8][4];
#pragma unroll
    for (int j = 0; j < 8; j++) { o[j][0]=0.f; o[j][1]=0.f; o[j][2]=0.f; o[j][3]=0.f; }
    float gmax0 = -1e30f, gmax1 = -1e30f, gs0 = 0.f, gs1 = 0.f;

    const int grow0 = n0 + wrow0 + gid;
    const float* mp0 = mask + (((size_t)(b*NH + h)*NN + grow0))*(size_t)NM + 2*t4;
    const float* mp1 = mp0 + (size_t)8 * NM;

    const int NIT = NM / 64;
    for (int it = 0; it < NIT; it++) {
        const int m0 = it * 64;
        if (it + 1 < NIT) {
            uint32_t st = sb + ((it + 1) & 1) * AST;
            const int m1 = m0 + 64;
            load_f16_tile_cp(st + A_KH, kh_g + (size_t)m1*NK, NK, 64);
            load_f16_tile_cp(st + A_KL, kl_g + (size_t)m1*NK, NK, 64);
            load_f16_tile_cp(st + A_VH, vh_g + (size_t)m1*NV, NV, 64);
            CP_COMMIT();
            PF_L2(pfb + m1);
            CP_WAIT1();
        } else {
            CP_WAIT0();
        }
        __syncthreads();
        const uint32_t st = sb + (it & 1) * AST;

        float c[8][4];
#pragma unroll
        for (int j = 0; j < 8; j++) { c[j][0]=0.f; c[j][1]=0.f; c[j][2]=0.f; c[j][3]=0.f; }
#pragma unroll
        for (int ks = 0; ks < 4; ks++) {
            uint32_t ql[4];
            ldsm_x4(ql, a_addr(sb + S_QL, wrow0, ks, lane));
            uint32_t bh[4][4], bl[4][4];
#pragma unroll
            for (int jp = 0; jp < 4; jp++)
                ldsm_x4(bh[jp], b_addr2(st + A_KH, 2*jp, ks, lane));
#pragma unroll
            for (int jp = 0; jp < 4; jp++)
                ldsm_x4(bl[jp], b_addr2(st + A_KL, 2*jp, ks, lane));
#pragma unroll
            for (int jp = 0; jp < 4; jp++) {
                mma16816(c[2*jp],   qh[ks], bh[jp][0], bh[jp][1]);
                mma16816(c[2*jp+1], qh[ks], bh[jp][2], bh[jp][3]);
            }
#pragma unroll
            for (int jp = 0; jp < 4; jp++) {
                mma16816(c[2*jp],   ql, bh[jp][0], bh[jp][1]);
                mma16816(c[2*jp+1], ql, bh[jp][2], bh[jp][3]);
            }
#pragma unroll
            for (int jp = 0; jp < 4; jp++) {
                mma16816(c[2*jp],   qh[ks], bl[jp][0], bl[jp][1]);
                mma16816(c[2*jp+1], qh[ks], bl[jp][2], bl[jp][3]);
            }
        }

        float mx0 = -1e30f, mx1 = -1e30f;
#pragma unroll
        for (int j = 0; j < 8; j++) {
            float2 a = *(const float2*)(mp0 + m0 + 8*j);
            float2 d = *(const float2*)(mp1 + m0 + 8*j);
            c[j][0] += a.x; c[j][1] += a.y; c[j][2] += d.x; c[j][3] += d.y;
            mx0 = fmaxf(mx0, fmaxf(c[j][0], c[j][1]));
            mx1 = fmaxf(mx1, fmaxf(c[j][2], c[j][3]));
        }
        mx0 = fmaxf(mx0, __shfl_xor_sync(0xffffffffu, mx0, 1));
        mx0 = fmaxf(mx0, __shfl_xor_sync(0xffffffffu, mx0, 2));
        mx1 = fmaxf(mx1, __shfl_xor_sync(0xffffffffu, mx1, 1));
        mx1 = fmaxf(mx1, __shfl_xor_sync(0xffffffffu, mx1, 2));

        float mn0 = fmaxf(gmax0, mx0), mn1 = fmaxf(gmax1, mx1);
        float sc0 = __expf(gmax0 - mn0), sc1 = __expf(gmax1 - mn1);
        gmax0 = mn0; gmax1 = mn1;

        uint32_t pk[8][2];
        float rs0 = 0.f, rs1 = 0.f;
#pragma unroll
        for (int j = 0; j < 8; j++) {
            __half2 t0 = __floats2half2_rn((c[j][0]-mn0)*L2E, (c[j][1]-mn0)*L2E);
            __half2 t1 = __floats2half2_rn((c[j][2]-mn1)*L2E, (c[j][3]-mn1)*L2E);
            pk[j][0] = ex2_h2(*(uint32_t*)&t0);
            pk[j][1] = ex2_h2(*(uint32_t*)&t1);
            float2 f0 = __half22float2(*(__half2*)&pk[j][0]);
            float2 f1 = __half22float2(*(__half2*)&pk[j][1]);
            rs0 += f0.x + f0.y; rs1 += f1.x + f1.y;
        }
        rs0 += __shfl_xor_sync(0xffffffffu, rs0, 1);
        rs0 += __shfl_xor_sync(0xffffffffu, rs0, 2);
        rs1 += __shfl_xor_sync(0xffffffffu, rs1, 1);
        rs1 += __shfl_xor_sync(0xffffffffu, rs1, 2);
        gs0 = gs0 * sc0 + rs0;
        gs1 = gs1 * sc1 + rs1;

#pragma unroll
        for (int j = 0; j < 8; j++) {
            o[j][0] *= sc0; o[j][1] *= sc0; o[j][2] *= sc1; o[j][3] *= sc1;
        }
#pragma unroll
        for (int ks = 0; ks < 4; ks++) {
            uint32_t pa[4] = { pk[2*ks][0], pk[2*ks][1], pk[2*ks+1][0], pk[2*ks+1][1] };
#pragma unroll
            for (int jv = 0; jv < 8; jv += 2) {
                uint32_t vh[4];
                ldsm_x4t(vh, v_addr2(st + A_VH, ks, jv, lane));
                mma16816(o[jv],   pa, vh[0], vh[1]);
                mma16816(o[jv+1], pa, vh[2], vh[3]);
            }
        }
        __syncthreads();
    }

    // epilogue: normalize, store O-hi only (fp16) [b][n][h][v]
    float inv0 = 1.0f / gs0, inv1 = 1.0f / gs1;
    size_t o0 = ((size_t)(b*NN + grow0)*NH + h)*NV + 2*t4;
    size_t o1 = ((size_t)(b*NN + grow0 + 8)*NH + h)*NV + 2*t4;
#pragma unroll
    for (int jv = 0; jv < 8; jv++) {
        *(__half2*)&g_Oh[o0 + 8*jv] = __floats2half2_rn(o[jv][0]*inv0, o[jv][1]*inv0);
        *(__half2*)&g_Oh[o1 + 8*jv] = __floats2half2_rn(o[jv][2]*inv1, o[jv][3]*inv1);
    }
}

// ---------------------------------------------------------------------------
// Kernel 4: output projection, 1-pass pure fp16 (O-hi x Po-hi).
// grid (ND/64, NN/128, NB).
// ---------------------------------------------------------------------------
__global__ void __launch_bounds__(256, 2)
out_proj_kernel(float* __restrict__ Y) {
    int b = blockIdx.z, n0 = blockIdx.y * 128, d0 = blockIdx.x * 64;
    float c[8][4] = {};
    gemm128x64<false, false, false>(g_Oh + (size_t)(b*NN + n0)*(NH*NV),
                                    nullptr, NH*NV,
                                    g_Poh + (size_t)d0*NV, nullptr, NV,
                                    (size_t)ND*NV, NH, c);
    int lane = threadIdx.x & 31, w = threadIdx.x >> 5;
    int gid = lane >> 2, t4 = lane & 3;
    int grow0 = n0 + w*16 + gid;
    size_t r0 = (size_t)(b*NN + grow0)*ND + d0;
#pragma unroll
    for (int j = 0; j < 8; j++) {
        int col = 8*j + 2*t4;
        *(float2*)&Y[r0 + col]        = make_float2(c[j][0], c[j][1]);
        *(float2*)&Y[r0 + 8*ND + col] = make_float2(c[j][2], c[j][3]);
    }
}

// ---------------------------------------------------------------------------
extern "C" void kernel_launch(void* const* d_in, const int* in_sizes, int n_in,
                              void* d_out, int out_size) {
    const float* X    = (const float*)d_in[0];
    const float* Mi   = (const float*)d_in[1];
    const float* mask = (const float*)d_in[2];
    const float* Pq   = (const float*)d_in[3];
    const float* Pk   = (const float*)d_in[4];
    const float* Pv   = (const float*)d_in[5];
    const float* Po   = (const float*)d_in[6];
    float* Y = (float*)d_out;

    cudaFuncSetAttribute(qkv_proj_kernel, cudaFuncAttributeMaxDynamicSharedMemorySize, SMEM_G);
    cudaFuncSetAttribute(attn_kernel,     cudaFuncAttributeMaxDynamicSharedMemorySize, SMEM_ATT);
    cudaFuncSetAttribute(out_proj_kernel, cudaFuncAttributeMaxDynamicSharedMemorySize, SMEM_G);

    split_all_kernel<<<dim3(2048, 6), 256>>>(X, Mi, Pq, Pk, Pv, Po);

    qkv_proj_kernel<<<dim3(NN/128, NH + 2, NB), 256, SMEM_G>>>();
    attn_kernel<<<dim3(NN/128, NH, NB), 256, SMEM_ATT>>>(mask);
    out_proj_kernel<<<dim3(ND/64, NN/128, NB), 256, SMEM_G>>>(Y);
}